// round 6
// baseline (speedup 1.0000x reference)
#include <cuda_runtime.h>
#include <cuda_fp16.h>
#include <math.h>
#include <cstdint>

#define BSZ 512
#define FD  512
#define HD  512
#define ED  8
#define OD  512

// ---------------- scratch (device globals; allocation is forbidden) ----------------
__device__ float d_h2[BSZ * HD];
__device__ float d_g [BSZ * ED];
__device__ float d_T [ED * BSZ * HD];

__device__ __align__(16) __half d_xhi[BSZ * FD], d_xlo[BSZ * FD];
__device__ __align__(16) __half d_ahi[BSZ * FD], d_alo[BSZ * FD];
__device__ __align__(16) __half d_g0h[HD * FD];
__device__ __align__(16) __half d_g1h[HD * HD];
__device__ __align__(16) __half d_w0h[ED * HD * FD];
__device__ __align__(16) __half d_w1h[ED * HD * HD];
__device__ __align__(16) __half d_w2h[ED * OD * HD];

__device__ __forceinline__ float elu1(float v) { return v > 0.f ? v : expm1f(v); }

__device__ __forceinline__ uint32_t smem_u32(const void* p) {
    uint32_t a;
    asm("{ .reg .u64 t; cvta.to.shared.u64 t, %1; cvt.u32.u64 %0, t; }" : "=r"(a) : "l"(p));
    return a;
}

#define CP16(dst, src) \
    asm volatile("cp.async.cg.shared.global [%0], [%1], 16;" :: "r"(dst), "l"(src))

#define LDSM4(r, addr) \
    asm volatile("ldmatrix.sync.aligned.m8n8.x4.shared.b16 {%0,%1,%2,%3}, [%4];" \
                 : "=r"((r)[0]), "=r"((r)[1]), "=r"((r)[2]), "=r"((r)[3]) : "r"(addr))

#define MMA16816F(d, a, b0, b1) \
    asm volatile("mma.sync.aligned.m16n8k16.row.col.f32.f16.f16.f32 " \
                 "{%0,%1,%2,%3},{%4,%5,%6,%7},{%8,%9},{%0,%1,%2,%3};" \
                 : "+f"((d)[0]), "+f"((d)[1]), "+f"((d)[2]), "+f"((d)[3]) \
                 : "r"((a)[0]), "r"((a)[1]), "r"((a)[2]), "r"((a)[3]), "r"(b0), "r"(b1))

__device__ __forceinline__ uint32_t pack_h2(float a, float b) {
    __half2 h = __floats2half2_rn(a, b);
    return *(uint32_t*)&h;
}

// ---------------- split-conversion: fp32 -> (hi, lo) fp16 (activations) ----------------
__global__ void __launch_bounds__(256)
conv_split(const float4* __restrict__ in, uint2* __restrict__ hi, uint2* __restrict__ lo, int n4) {
    int i = blockIdx.x * 256 + threadIdx.x;
    if (i >= n4) return;
    float4 v = in[i];
    float h0 = __half2float(__float2half_rn(v.x));
    float h1 = __half2float(__float2half_rn(v.y));
    float h2 = __half2float(__float2half_rn(v.z));
    float h3 = __half2float(__float2half_rn(v.w));
    uint2 H, L;
    H.x = pack_h2(h0, h1); H.y = pack_h2(h2, h3);
    L.x = pack_h2(v.x - h0, v.y - h1);
    L.y = pack_h2(v.z - h2, v.w - h3);
    hi[i] = H; lo[i] = L;
}

// ---------------- plain fp32 -> fp16 conversion (weights) ----------------
__global__ void __launch_bounds__(256)
conv_half(const float4* __restrict__ in, uint2* __restrict__ hi, int n4) {
    int i = blockIdx.x * 256 + threadIdx.x;
    if (i >= n4) return;
    float4 v = in[i];
    uint2 H;
    H.x = pack_h2(v.x, v.y); H.y = pack_h2(v.z, v.w);
    hi[i] = H;
}

// ---------------- fused 2-pass split GEMM ----------------
// acc = Ahi·Bh^T + Alo·Bh^T over K=512, tile 128x128, BK=64, 3-stage cp.async.
// Stage: [Ahi 16K][Alo 16K][Bh 16K] = 48KB.
// mode: 0 = plain fp32 out; 1 = bias+elu fp32 out; 2 = bias+elu, split fp16 hi/lo out.
__global__ void __launch_bounds__(256)
tgemm_fused(const __half* __restrict__ Axhi, const __half* __restrict__ Axlo,
            const __half* __restrict__ Bwh,
            const float* __restrict__ bias, float* __restrict__ C,
            __half* __restrict__ Ohi, __half* __restrict__ Olo,
            long strideW, long strideC, int mode)
{
    extern __shared__ __align__(128) char smem[];
    const uint32_t sb = smem_u32(smem);
    const int tid = threadIdx.x;
    const int wid = tid >> 5, lane = tid & 31;
    const int e = blockIdx.z;
    const int bm = blockIdx.y * 128, bn = blockIdx.x * 128;
    Bwh += (long)e * strideW;
    C   += (long)e * strideC;

    const int lsub = tid >> 3;   // 0..31
    const int lc16 = tid & 7;

    const __half* tp[3] = { Axhi, Axlo, Bwh };
    const int toff[3] = { bm, bm, bn };

    auto load_stage = [&](int kc, int buf) {
        const int k0 = kc << 6;
        const uint32_t base = sb + (uint32_t)buf * 49152u;
        #pragma unroll
        for (int t = 0; t < 3; t++) {
            const __half* P = tp[t];
            #pragma unroll
            for (int it = 0; it < 4; it++) {
                const int row = it * 32 + lsub;
                const uint32_t dst = base + (uint32_t)t * 16384u
                                   + (uint32_t)(row * 128 + ((lc16 ^ (row & 7)) << 4));
                CP16(dst, P + (long)(toff[t] + row) * 512 + k0 + lc16 * 8);
            }
        }
    };

    const int warpM = wid & 3, warpN = wid >> 2;
    const int arow = warpM * 32 + (lane & 15);
    const uint32_t aswz = (uint32_t)(arow & 7);
    const uint32_t ahalf = (uint32_t)(lane >> 4);
    const int q = lane >> 3;
    const int brow_base = warpN * 64 + ((q >> 1) << 3) + (lane & 7);
    const uint32_t bk = (uint32_t)(q & 1);

    float acc[2][8][4] = {};

    load_stage(0, 0);
    asm volatile("cp.async.commit_group;" ::: "memory");
    load_stage(1, 1);
    asm volatile("cp.async.commit_group;" ::: "memory");

    for (int c = 0; c < 8; c++) {
        if (c < 7) asm volatile("cp.async.wait_group 1;" ::: "memory");
        else       asm volatile("cp.async.wait_group 0;" ::: "memory");
        __syncthreads();
        if (c + 2 < 8) {
            load_stage(c + 2, (c + 2) % 3);
            asm volatile("cp.async.commit_group;" ::: "memory");
        }

        const uint32_t S   = sb + (uint32_t)(c % 3) * 49152u;
        const uint32_t Ahi = S, Alo = S + 16384u, Bh = S + 32768u;

        #pragma unroll
        for (int ks = 0; ks < 4; ks++) {
            const uint32_t achunk = (((uint32_t)(ks << 1) + ahalf) ^ aswz) << 4;
            uint32_t ah[2][4], al[2][4];
            #pragma unroll
            for (int mi = 0; mi < 2; mi++) {
                const uint32_t roff = (uint32_t)((arow + mi * 16) * 128);
                LDSM4(ah[mi], Ahi + roff + achunk);
                LDSM4(al[mi], Alo + roff + achunk);
            }
            uint32_t b[4][4];
            #pragma unroll
            for (int np = 0; np < 4; np++) {
                const int brow = brow_base + np * 16;
                const uint32_t boff = (uint32_t)(brow * 128)
                                    + ((((uint32_t)(ks << 1) + bk) ^ (uint32_t)(brow & 7)) << 4);
                LDSM4(b[np], Bh + boff);
            }
            #pragma unroll
            for (int mi = 0; mi < 2; mi++)
                #pragma unroll
                for (int ni = 0; ni < 8; ni++) {
                    MMA16816F(acc[mi][ni], ah[mi], b[ni >> 1][(ni & 1) * 2],
                              b[ni >> 1][(ni & 1) * 2 + 1]);
                    MMA16816F(acc[mi][ni], al[mi], b[ni >> 1][(ni & 1) * 2],
                              b[ni >> 1][(ni & 1) * 2 + 1]);
                }
        }
        __syncthreads();
    }

    const int gr = lane >> 2, gc = (lane & 3) * 2;
    #pragma unroll
    for (int mi = 0; mi < 2; mi++) {
        const int row0 = bm + warpM * 32 + mi * 16 + gr;
        #pragma unroll
        for (int ni = 0; ni < 8; ni++) {
            const int col = bn + warpN * 64 + ni * 8 + gc;
            float v0 = acc[mi][ni][0], v1 = acc[mi][ni][1];
            float v2 = acc[mi][ni][2], v3 = acc[mi][ni][3];
            if (mode != 0) {
                const float b0 = bias[col], b1 = bias[col + 1];
                v0 = elu1(v0 + b0); v1 = elu1(v1 + b1);
                v2 = elu1(v2 + b0); v3 = elu1(v3 + b1);
            }
            if (mode == 2) {
                float h0f = __half2float(__float2half_rn(v0));
                float h1f = __half2float(__float2half_rn(v1));
                float h2f = __half2float(__float2half_rn(v2));
                float h3f = __half2float(__float2half_rn(v3));
                *(uint32_t*)&Ohi[(long)row0 * 512 + col]       = pack_h2(h0f, h1f);
                *(uint32_t*)&Olo[(long)row0 * 512 + col]       = pack_h2(v0 - h0f, v1 - h1f);
                *(uint32_t*)&Ohi[(long)(row0 + 8) * 512 + col] = pack_h2(h2f, h3f);
                *(uint32_t*)&Olo[(long)(row0 + 8) * 512 + col] = pack_h2(v2 - h2f, v3 - h3f);
            } else {
                *(float2*)&C[(long)row0 * 512 + col]       = make_float2(v0, v1);
                *(float2*)&C[(long)(row0 + 8) * 512 + col] = make_float2(v2, v3);
            }
        }
    }
}

// ---------------- gating softmax ----------------
__global__ void __launch_bounds__(256)
gate_kernel(const float* __restrict__ h, const float* __restrict__ w2,
            const float* __restrict__ b2, float* __restrict__ g)
{
    __shared__ float s[512];
    __shared__ float lg[8];
    const int b = blockIdx.x, tid = threadIdx.x;
    for (int i = tid; i < 512; i += 256) s[i] = h[(long)b * 512 + i];
    __syncthreads();

    const int w = tid >> 5, lane = tid & 31;
    float sum = 0.f;
    for (int i = lane; i < 512; i += 32) sum += s[i] * w2[(long)w * 512 + i];
    #pragma unroll
    for (int o = 16; o > 0; o >>= 1) sum += __shfl_xor_sync(0xffffffffu, sum, o);
    if (lane == 0) lg[w] = sum + b2[w];
    __syncthreads();

    if (tid == 0) {
        float mx = lg[0];
        #pragma unroll
        for (int i = 1; i < 8; i++) mx = fmaxf(mx, lg[i]);
        float ex[8], se = 0.f;
        #pragma unroll
        for (int i = 0; i < 8; i++) { ex[i] = expf(lg[i] - mx); se += ex[i]; }
        float inv = 1.f / se;
        #pragma unroll
        for (int i = 0; i < 8; i++) g[(long)b * 8 + i] = ex[i] * inv;
    }
}

// ---------------- gated blend (float4, 1/thread) ----------------
// mode 0: out fp32, no elu (final). mode 1: elu then split fp16 hi/lo.
__global__ void __launch_bounds__(256)
blend_kernel(const float4* __restrict__ T4, const float* __restrict__ g,
             const float4* __restrict__ beta4, float* __restrict__ out,
             __half* __restrict__ Ohi, __half* __restrict__ Olo, int mode)
{
    const int i4 = blockIdx.x * 256 + threadIdx.x;     // 65536 float4s
    const int base = i4 << 2;
    const int b = base >> 9, h4 = (base & 511) >> 2;
    float4 sum = make_float4(0.f, 0.f, 0.f, 0.f);
    #pragma unroll
    for (int e = 0; e < 8; e++) {
        const float ge = g[b * 8 + e];
        const float4 t = T4[(e << 16) + i4];
        const float4 be = beta4[(e << 7) + h4];
        sum.x += ge * (t.x + be.x); sum.y += ge * (t.y + be.y);
        sum.z += ge * (t.z + be.z); sum.w += ge * (t.w + be.w);
    }
    if (mode == 0) {
        ((float4*)out)[i4] = sum;
    } else {
        sum.x = elu1(sum.x); sum.y = elu1(sum.y); sum.z = elu1(sum.z); sum.w = elu1(sum.w);
        float h0 = __half2float(__float2half_rn(sum.x));
        float h1 = __half2float(__float2half_rn(sum.y));
        float h2 = __half2float(__float2half_rn(sum.z));
        float h3 = __half2float(__float2half_rn(sum.w));
        uint2 H, L;
        H.x = pack_h2(h0, h1); H.y = pack_h2(h2, h3);
        L.x = pack_h2(sum.x - h0, sum.y - h1);
        L.y = pack_h2(sum.z - h2, sum.w - h3);
        ((uint2*)Ohi)[i4] = H;
        ((uint2*)Olo)[i4] = L;
    }
}

// ---------------- launch ----------------
extern "C" void kernel_launch(void* const* d_in, const int* in_sizes, int n_in,
                              void* d_out, int out_size)
{
    const float* x      = (const float*)d_in[0];
    const float* gw0    = (const float*)d_in[1];
    const float* gb0    = (const float*)d_in[2];
    const float* gw1    = (const float*)d_in[3];
    const float* gb1    = (const float*)d_in[4];
    const float* gw2    = (const float*)d_in[5];
    const float* gb2    = (const float*)d_in[6];
    const float* alpha0 = (const float*)d_in[7];
    const float* beta0  = (const float*)d_in[8];
    const float* alpha1 = (const float*)d_in[9];
    const float* beta1  = (const float*)d_in[10];
    const float* alpha2 = (const float*)d_in[11];
    const float* beta2  = (const float*)d_in[12];
    float* out = (float*)d_out;

    float *h2, *gp, *T;
    cudaGetSymbolAddress((void**)&h2, d_h2);
    cudaGetSymbolAddress((void**)&gp, d_g);
    cudaGetSymbolAddress((void**)&T,  d_T);

    __half *xhi, *xlo, *ahi, *alo, *g0h, *g1h, *w0h, *w1h, *w2h;
    cudaGetSymbolAddress((void**)&xhi, d_xhi); cudaGetSymbolAddress((void**)&xlo, d_xlo);
    cudaGetSymbolAddress((void**)&ahi, d_ahi); cudaGetSymbolAddress((void**)&alo, d_alo);
    cudaGetSymbolAddress((void**)&g0h, d_g0h); cudaGetSymbolAddress((void**)&g1h, d_g1h);
    cudaGetSymbolAddress((void**)&w0h, d_w0h); cudaGetSymbolAddress((void**)&w1h, d_w1h);
    cudaGetSymbolAddress((void**)&w2h, d_w2h);

    const int SMEM_SZ = 3 * 49152;  // 3 stages x (Ahi+Alo+Bh)
    cudaFuncSetAttribute(tgemm_fused, cudaFuncAttributeMaxDynamicSharedMemorySize, SMEM_SZ);

    const int NSMALL4 = (512 * 512) / 4;
    const int NBIG4   = (8 * 512 * 512) / 4;
    const long sW = 512L * 512, sC = 512L * 512;
    dim3 g1(4, 4, 1), g8(4, 4, 8);
    const int BLEND_B = (BSZ * HD / 4) / 256;  // 256 blocks

    // conversions (x split; weights plain fp16)
    conv_split<<<NSMALL4 / 256, 256>>>((const float4*)x, (uint2*)xhi, (uint2*)xlo, NSMALL4);
    conv_half<<<NSMALL4 / 256, 256>>>((const float4*)gw0, (uint2*)g0h, NSMALL4);
    conv_half<<<NSMALL4 / 256, 256>>>((const float4*)gw1, (uint2*)g1h, NSMALL4);
    conv_half<<<NBIG4 / 256, 256>>>((const float4*)alpha0, (uint2*)w0h, NBIG4);
    conv_half<<<NBIG4 / 256, 256>>>((const float4*)alpha1, (uint2*)w1h, NBIG4);
    conv_half<<<NBIG4 / 256, 256>>>((const float4*)alpha2, (uint2*)w2h, NBIG4);

    // gating MLP (layer1 writes split fp16 directly; layer2 fp32 for softmax)
    tgemm_fused<<<g1, 256, SMEM_SZ>>>(xhi, xlo, g0h, gb0, nullptr, ahi, alo, 0, 0, 2);
    tgemm_fused<<<g1, 256, SMEM_SZ>>>(ahi, alo, g1h, gb1, h2, nullptr, nullptr, 0, 0, 1);
    gate_kernel<<<BSZ, 256>>>(h2, gw2, gb2, gp);

    // expert layer 1
    tgemm_fused<<<g8, 256, SMEM_SZ>>>(xhi, xlo, w0h, nullptr, T, nullptr, nullptr, sW, sC, 0);
    blend_kernel<<<BLEND_B, 256>>>((const float4*)T, gp, (const float4*)beta0, nullptr, ahi, alo, 1);

    // expert layer 2
    tgemm_fused<<<g8, 256, SMEM_SZ>>>(ahi, alo, w1h, nullptr, T, nullptr, nullptr, sW, sC, 0);
    blend_kernel<<<BLEND_B, 256>>>((const float4*)T, gp, (const float4*)beta1, nullptr, ahi, alo, 1);

    // expert layer 3 (final: fp32, no activation)
    tgemm_fused<<<g8, 256, SMEM_SZ>>>(ahi, alo, w2h, nullptr, T, nullptr, nullptr, sW, sC, 0);
    blend_kernel<<<BLEND_B, 256>>>((const float4*)T, gp, (const float4*)beta2, out, nullptr, nullptr, 0);
}

// round 7
// speedup vs baseline: 1.2339x; 1.2339x over previous
#include <cuda_runtime.h>
#include <cuda_bf16.h>
#include <math.h>
#include <cstdint>

#define BSZ 512
#define FD  512
#define HD  512
#define ED  8
#define OD  512

// ---------------- scratch (device globals; allocation is forbidden) ----------------
__device__ float d_h2[BSZ * HD];
__device__ float d_g [BSZ * ED];
__device__ float d_T [ED * BSZ * HD];

__device__ __align__(16) __nv_bfloat16 d_xhi[BSZ * FD], d_xlo[BSZ * FD];
__device__ __align__(16) __nv_bfloat16 d_ahi[BSZ * FD], d_alo[BSZ * FD];
__device__ __align__(16) __nv_bfloat16 d_g0hi[HD * FD], d_g0lo[HD * FD];
__device__ __align__(16) __nv_bfloat16 d_g1hi[HD * HD], d_g1lo[HD * HD];
__device__ __align__(16) __nv_bfloat16 d_w0hi[ED * HD * FD], d_w0lo[ED * HD * FD];
__device__ __align__(16) __nv_bfloat16 d_w1hi[ED * HD * HD], d_w1lo[ED * HD * HD];
__device__ __align__(16) __nv_bfloat16 d_w2hi[ED * OD * HD], d_w2lo[ED * OD * HD];

__device__ __forceinline__ float elu1(float v) { return v > 0.f ? v : expm1f(v); }

__device__ __forceinline__ uint32_t smem_u32(const void* p) {
    uint32_t a;
    asm("{ .reg .u64 t; cvta.to.shared.u64 t, %1; cvt.u32.u64 %0, t; }" : "=r"(a) : "l"(p));
    return a;
}

#define CP16(dst, src) \
    asm volatile("cp.async.cg.shared.global [%0], [%1], 16;" :: "r"(dst), "l"(src))

#define LDSM4(r, addr) \
    asm volatile("ldmatrix.sync.aligned.m8n8.x4.shared.b16 {%0,%1,%2,%3}, [%4];" \
                 : "=r"((r)[0]), "=r"((r)[1]), "=r"((r)[2]), "=r"((r)[3]) : "r"(addr))

#define MMA16816(d, a, b0, b1) \
    asm volatile("mma.sync.aligned.m16n8k16.row.col.f32.bf16.bf16.f32 " \
                 "{%0,%1,%2,%3},{%4,%5,%6,%7},{%8,%9},{%0,%1,%2,%3};" \
                 : "+f"((d)[0]), "+f"((d)[1]), "+f"((d)[2]), "+f"((d)[3]) \
                 : "r"((a)[0]), "r"((a)[1]), "r"((a)[2]), "r"((a)[3]), "r"(b0), "r"(b1))

__device__ __forceinline__ uint32_t pack_bf16x2(float a, float b) {
    uint32_t r;
    asm("cvt.rn.bf16x2.f32 %0, %1, %2;" : "=r"(r) : "f"(b), "f"(a));
    return r;
}

// ---------------- split-conversion: fp32 -> (hi, lo) bf16 ----------------
__device__ __forceinline__ void split_one(const float4* in, uint2* hi, uint2* lo, int i) {
    float4 v = in[i];
    float h0 = __bfloat162float(__float2bfloat16(v.x));
    float h1 = __bfloat162float(__float2bfloat16(v.y));
    float h2 = __bfloat162float(__float2bfloat16(v.z));
    float h3 = __bfloat162float(__float2bfloat16(v.w));
    uint2 H, L;
    H.x = pack_bf16x2(h0, h1); H.y = pack_bf16x2(h2, h3);
    L.x = pack_bf16x2(v.x - h0, v.y - h1);
    L.y = pack_bf16x2(v.z - h2, v.w - h3);
    hi[i] = H; lo[i] = L;
}

__global__ void __launch_bounds__(256)
conv_split(const float4* __restrict__ in, uint2* __restrict__ hi, uint2* __restrict__ lo, int n4) {
    int i = blockIdx.x * 256 + threadIdx.x;
    if (i < n4) split_one(in, hi, lo, i);
}

// merged: 3 big weight tensors in one launch (2048 blocks each)
__global__ void __launch_bounds__(256)
conv_split3(const float4* __restrict__ in0, uint2* __restrict__ hi0, uint2* __restrict__ lo0,
            const float4* __restrict__ in1, uint2* __restrict__ hi1, uint2* __restrict__ lo1,
            const float4* __restrict__ in2, uint2* __restrict__ hi2, uint2* __restrict__ lo2)
{
    const int t = blockIdx.x >> 11;               // /2048
    const int i = (blockIdx.x & 2047) * 256 + threadIdx.x;
    if (t == 0)      split_one(in0, hi0, lo0, i);
    else if (t == 1) split_one(in1, hi1, lo1, i);
    else             split_one(in2, hi2, lo2, i);
}

// merged: 2 gating weight tensors (256 blocks each)
__global__ void __launch_bounds__(256)
conv_split2(const float4* __restrict__ in0, uint2* __restrict__ hi0, uint2* __restrict__ lo0,
            const float4* __restrict__ in1, uint2* __restrict__ hi1, uint2* __restrict__ lo1)
{
    const int t = blockIdx.x >> 8;                // /256
    const int i = (blockIdx.x & 255) * 256 + threadIdx.x;
    if (t == 0) split_one(in0, hi0, lo0, i);
    else        split_one(in1, hi1, lo1, i);
}

// ---------------- fused 3-pass split GEMM ----------------
// acc = Ahi·Bhi^T + Alo·Bhi^T + Ahi·Blo^T over K=512, tile 128x128, BK=64.
// Per stage loads 4 tiles (Ahi,Alo,Bhi,Blo) = 64KB; 3 stages (192KB smem); 8 K-iters.
// mode: 0 = plain fp32 out; 1 = bias+elu fp32 out; 2 = bias+elu, split bf16 hi/lo out.
__global__ void __launch_bounds__(256)
tgemm_fused(const __nv_bfloat16* __restrict__ Axhi, const __nv_bfloat16* __restrict__ Axlo,
            const __nv_bfloat16* __restrict__ Bwhi, const __nv_bfloat16* __restrict__ Bwlo,
            const float* __restrict__ bias, float* __restrict__ C,
            __nv_bfloat16* __restrict__ Ohi, __nv_bfloat16* __restrict__ Olo,
            long strideW, long strideC, int mode)
{
    extern __shared__ __align__(128) char smem[];
    const uint32_t sb = smem_u32(smem);
    const int tid = threadIdx.x;
    const int wid = tid >> 5, lane = tid & 31;
    const int e = blockIdx.z;
    const int bm = blockIdx.y * 128, bn = blockIdx.x * 128;
    Bwhi += (long)e * strideW;
    Bwlo += (long)e * strideW;
    C    += (long)e * strideC;

    const int lsub = tid >> 3;   // 0..31
    const int lc16 = tid & 7;

    const __nv_bfloat16* tp[4] = { Axhi, Axlo, Bwhi, Bwlo };
    const int toff[4] = { bm, bm, bn, bn };

    auto load_stage = [&](int kc, int buf) {
        const int k0 = kc << 6;
        const uint32_t base = sb + (uint32_t)buf * 65536u;
        #pragma unroll
        for (int t = 0; t < 4; t++) {
            const __nv_bfloat16* P = tp[t];
            #pragma unroll
            for (int it = 0; it < 4; it++) {
                const int row = it * 32 + lsub;
                const uint32_t dst = base + (uint32_t)t * 16384u
                                   + (uint32_t)(row * 128 + ((lc16 ^ (row & 7)) << 4));
                CP16(dst, P + (long)(toff[t] + row) * 512 + k0 + lc16 * 8);
            }
        }
    };

    const int warpM = wid & 3, warpN = wid >> 2;
    const int arow = warpM * 32 + (lane & 15);
    const uint32_t aswz = (uint32_t)(arow & 7);
    const uint32_t ahalf = (uint32_t)(lane >> 4);
    const int q = lane >> 3;
    const int brow_base = warpN * 64 + ((q >> 1) << 3) + (lane & 7);
    const uint32_t bk = (uint32_t)(q & 1);

    float acc[2][8][4] = {};

    load_stage(0, 0);
    asm volatile("cp.async.commit_group;" ::: "memory");
    load_stage(1, 1);
    asm volatile("cp.async.commit_group;" ::: "memory");

    for (int c = 0; c < 8; c++) {
        if (c < 7) asm volatile("cp.async.wait_group 1;" ::: "memory");
        else       asm volatile("cp.async.wait_group 0;" ::: "memory");
        __syncthreads();
        if (c + 2 < 8) {
            load_stage(c + 2, (c + 2) % 3);
            asm volatile("cp.async.commit_group;" ::: "memory");
        }

        const uint32_t S   = sb + (uint32_t)(c % 3) * 65536u;
        const uint32_t Ahi = S, Alo = S + 16384u, Bhi = S + 32768u, Blo = S + 49152u;

        #pragma unroll
        for (int ks = 0; ks < 4; ks++) {
            const uint32_t achunk = (((uint32_t)(ks << 1) + ahalf) ^ aswz) << 4;
            uint32_t ah[2][4], al[2][4];
            #pragma unroll
            for (int mi = 0; mi < 2; mi++) {
                const uint32_t roff = (uint32_t)((arow + mi * 16) * 128);
                LDSM4(ah[mi], Ahi + roff + achunk);
                LDSM4(al[mi], Alo + roff + achunk);
            }
            uint32_t b[4][4];
            #pragma unroll
            for (int np = 0; np < 4; np++) {
                const int brow = brow_base + np * 16;
                const uint32_t boff = (uint32_t)(brow * 128)
                                    + ((((uint32_t)(ks << 1) + bk) ^ (uint32_t)(brow & 7)) << 4);
                LDSM4(b[np], Bhi + boff);
            }
            #pragma unroll
            for (int mi = 0; mi < 2; mi++)
                #pragma unroll
                for (int ni = 0; ni < 8; ni++) {
                    MMA16816(acc[mi][ni], ah[mi], b[ni >> 1][(ni & 1) * 2],
                             b[ni >> 1][(ni & 1) * 2 + 1]);
                    MMA16816(acc[mi][ni], al[mi], b[ni >> 1][(ni & 1) * 2],
                             b[ni >> 1][(ni & 1) * 2 + 1]);
                }
            #pragma unroll
            for (int np = 0; np < 4; np++) {
                const int brow = brow_base + np * 16;
                const uint32_t boff = (uint32_t)(brow * 128)
                                    + ((((uint32_t)(ks << 1) + bk) ^ (uint32_t)(brow & 7)) << 4);
                LDSM4(b[np], Blo + boff);
            }
            #pragma unroll
            for (int mi = 0; mi < 2; mi++)
                #pragma unroll
                for (int ni = 0; ni < 8; ni++)
                    MMA16816(acc[mi][ni], ah[mi], b[ni >> 1][(ni & 1) * 2],
                             b[ni >> 1][(ni & 1) * 2 + 1]);
        }
        __syncthreads();
    }

    const int gr = lane >> 2, gc = (lane & 3) * 2;
    #pragma unroll
    for (int mi = 0; mi < 2; mi++) {
        const int row0 = bm + warpM * 32 + mi * 16 + gr;
        #pragma unroll
        for (int ni = 0; ni < 8; ni++) {
            const int col = bn + warpN * 64 + ni * 8 + gc;
            float v0 = acc[mi][ni][0], v1 = acc[mi][ni][1];
            float v2 = acc[mi][ni][2], v3 = acc[mi][ni][3];
            if (mode != 0) {
                const float b0 = bias[col], b1 = bias[col + 1];
                v0 = elu1(v0 + b0); v1 = elu1(v1 + b1);
                v2 = elu1(v2 + b0); v3 = elu1(v3 + b1);
            }
            if (mode == 2) {
                float h0f = __bfloat162float(__float2bfloat16(v0));
                float h1f = __bfloat162float(__float2bfloat16(v1));
                float h2f = __bfloat162float(__float2bfloat16(v2));
                float h3f = __bfloat162float(__float2bfloat16(v3));
                *(uint32_t*)&Ohi[(long)row0 * 512 + col]       = pack_bf16x2(h0f, h1f);
                *(uint32_t*)&Olo[(long)row0 * 512 + col]       = pack_bf16x2(v0 - h0f, v1 - h1f);
                *(uint32_t*)&Ohi[(long)(row0 + 8) * 512 + col] = pack_bf16x2(h2f, h3f);
                *(uint32_t*)&Olo[(long)(row0 + 8) * 512 + col] = pack_bf16x2(v2 - h2f, v3 - h3f);
            } else {
                *(float2*)&C[(long)row0 * 512 + col]       = make_float2(v0, v1);
                *(float2*)&C[(long)(row0 + 8) * 512 + col] = make_float2(v2, v3);
            }
        }
    }
}

// ---------------- gating softmax ----------------
__global__ void __launch_bounds__(256)
gate_kernel(const float* __restrict__ h, const float* __restrict__ w2,
            const float* __restrict__ b2, float* __restrict__ g)
{
    __shared__ float s[512];
    __shared__ float lg[8];
    const int b = blockIdx.x, tid = threadIdx.x;
    for (int i = tid; i < 512; i += 256) s[i] = h[(long)b * 512 + i];
    __syncthreads();

    const int w = tid >> 5, lane = tid & 31;
    float sum = 0.f;
    for (int i = lane; i < 512; i += 32) sum += s[i] * w2[(long)w * 512 + i];
    #pragma unroll
    for (int o = 16; o > 0; o >>= 1) sum += __shfl_xor_sync(0xffffffffu, sum, o);
    if (lane == 0) lg[w] = sum + b2[w];
    __syncthreads();

    if (tid == 0) {
        float mx = lg[0];
        #pragma unroll
        for (int i = 1; i < 8; i++) mx = fmaxf(mx, lg[i]);
        float ex[8], se = 0.f;
        #pragma unroll
        for (int i = 0; i < 8; i++) { ex[i] = expf(lg[i] - mx); se += ex[i]; }
        float inv = 1.f / se;
        #pragma unroll
        for (int i = 0; i < 8; i++) g[(long)b * 8 + i] = ex[i] * inv;
    }
}

// ---------------- gated blend (float4) ----------------
// mode 0: out fp32, no elu (final). mode 1: elu then split bf16 hi/lo.
__global__ void __launch_bounds__(256)
blend_kernel(const float4* __restrict__ T4, const float* __restrict__ g,
             const float4* __restrict__ beta4, float* __restrict__ out,
             __nv_bfloat16* __restrict__ Ohi, __nv_bfloat16* __restrict__ Olo, int mode)
{
    const int i4 = blockIdx.x * 256 + threadIdx.x;     // 65536 float4s
    const int base = i4 << 2;
    const int b = base >> 9, h4 = (base & 511) >> 2;
    float4 sum = make_float4(0.f, 0.f, 0.f, 0.f);
    #pragma unroll
    for (int e = 0; e < 8; e++) {
        const float ge = g[b * 8 + e];
        const float4 t = T4[(e << 16) + i4];
        const float4 be = beta4[(e << 7) + h4];
        sum.x += ge * (t.x + be.x); sum.y += ge * (t.y + be.y);
        sum.z += ge * (t.z + be.z); sum.w += ge * (t.w + be.w);
    }
    if (mode == 0) {
        ((float4*)out)[i4] = sum;
    } else {
        sum.x = elu1(sum.x); sum.y = elu1(sum.y); sum.z = elu1(sum.z); sum.w = elu1(sum.w);
        float h0 = __bfloat162float(__float2bfloat16(sum.x));
        float h1 = __bfloat162float(__float2bfloat16(sum.y));
        float h2 = __bfloat162float(__float2bfloat16(sum.z));
        float h3 = __bfloat162float(__float2bfloat16(sum.w));
        uint2 H, L;
        H.x = pack_bf16x2(h0, h1); H.y = pack_bf16x2(h2, h3);
        L.x = pack_bf16x2(sum.x - h0, sum.y - h1);
        L.y = pack_bf16x2(sum.z - h2, sum.w - h3);
        ((uint2*)Ohi)[i4] = H;
        ((uint2*)Olo)[i4] = L;
    }
}

// ---------------- launch ----------------
extern "C" void kernel_launch(void* const* d_in, const int* in_sizes, int n_in,
                              void* d_out, int out_size)
{
    const float* x      = (const float*)d_in[0];
    const float* gw0    = (const float*)d_in[1];
    const float* gb0    = (const float*)d_in[2];
    const float* gw1    = (const float*)d_in[3];
    const float* gb1    = (const float*)d_in[4];
    const float* gw2    = (const float*)d_in[5];
    const float* gb2    = (const float*)d_in[6];
    const float* alpha0 = (const float*)d_in[7];
    const float* beta0  = (const float*)d_in[8];
    const float* alpha1 = (const float*)d_in[9];
    const float* beta1  = (const float*)d_in[10];
    const float* alpha2 = (const float*)d_in[11];
    const float* beta2  = (const float*)d_in[12];
    float* out = (float*)d_out;

    float *h2, *gp, *T;
    cudaGetSymbolAddress((void**)&h2, d_h2);
    cudaGetSymbolAddress((void**)&gp, d_g);
    cudaGetSymbolAddress((void**)&T,  d_T);

    __nv_bfloat16 *xhi, *xlo, *ahi, *alo, *g0hi, *g0lo, *g1hi, *g1lo;
    __nv_bfloat16 *w0hi, *w0lo, *w1hi, *w1lo, *w2hi, *w2lo;
    cudaGetSymbolAddress((void**)&xhi,  d_xhi);  cudaGetSymbolAddress((void**)&xlo,  d_xlo);
    cudaGetSymbolAddress((void**)&ahi,  d_ahi);  cudaGetSymbolAddress((void**)&alo,  d_alo);
    cudaGetSymbolAddress((void**)&g0hi, d_g0hi); cudaGetSymbolAddress((void**)&g0lo, d_g0lo);
    cudaGetSymbolAddress((void**)&g1hi, d_g1hi); cudaGetSymbolAddress((void**)&g1lo, d_g1lo);
    cudaGetSymbolAddress((void**)&w0hi, d_w0hi); cudaGetSymbolAddress((void**)&w0lo, d_w0lo);
    cudaGetSymbolAddress((void**)&w1hi, d_w1hi); cudaGetSymbolAddress((void**)&w1lo, d_w1lo);
    cudaGetSymbolAddress((void**)&w2hi, d_w2hi); cudaGetSymbolAddress((void**)&w2lo, d_w2lo);

    const int SMEM_SZ = 3 * 65536;  // 3 stages x (Ahi+Alo+Bhi+Blo)
    cudaFuncSetAttribute(tgemm_fused, cudaFuncAttributeMaxDynamicSharedMemorySize, SMEM_SZ);

    const int NSMALL4 = (512 * 512) / 4;
    const long sW = 512L * 512, sC = 512L * 512;
    dim3 g1(4, 4, 1), g8(4, 4, 8);
    const int BLEND_B = (BSZ * HD / 4) / 256;  // 256 blocks

    // split conversions (x single; gating weights merged x2; expert weights merged x3)
    conv_split<<<NSMALL4 / 256, 256>>>((const float4*)x, (uint2*)xhi, (uint2*)xlo, NSMALL4);
    conv_split2<<<2 * 256, 256>>>((const float4*)gw0, (uint2*)g0hi, (uint2*)g0lo,
                                  (const float4*)gw1, (uint2*)g1hi, (uint2*)g1lo);
    conv_split3<<<3 * 2048, 256>>>((const float4*)alpha0, (uint2*)w0hi, (uint2*)w0lo,
                                   (const float4*)alpha1, (uint2*)w1hi, (uint2*)w1lo,
                                   (const float4*)alpha2, (uint2*)w2hi, (uint2*)w2lo);

    // gating MLP (layer1 writes split bf16 directly; layer2 fp32 for softmax)
    tgemm_fused<<<g1, 256, SMEM_SZ>>>(xhi, xlo, g0hi, g0lo, gb0, nullptr, ahi, alo, 0, 0, 2);
    tgemm_fused<<<g1, 256, SMEM_SZ>>>(ahi, alo, g1hi, g1lo, gb1, h2, nullptr, nullptr, 0, 0, 1);
    gate_kernel<<<BSZ, 256>>>(h2, gw2, gb2, gp);

    // expert layer 1
    tgemm_fused<<<g8, 256, SMEM_SZ>>>(xhi, xlo, w0hi, w0lo, nullptr, T, nullptr, nullptr, sW, sC, 0);
    blend_kernel<<<BLEND_B, 256>>>((const float4*)T, gp, (const float4*)beta0, nullptr, ahi, alo, 1);

    // expert layer 2
    tgemm_fused<<<g8, 256, SMEM_SZ>>>(ahi, alo, w1hi, w1lo, nullptr, T, nullptr, nullptr, sW, sC, 0);
    blend_kernel<<<BLEND_B, 256>>>((const float4*)T, gp, (const float4*)beta1, nullptr, ahi, alo, 1);

    // expert layer 3 (final: fp32, no activation)
    tgemm_fused<<<g8, 256, SMEM_SZ>>>(ahi, alo, w2hi, w2lo, nullptr, T, nullptr, nullptr, sW, sC, 0);
    blend_kernel<<<BLEND_B, 256>>>((const float4*)T, gp, (const float4*)beta2, out, nullptr, nullptr, 0);
}

// round 8
// speedup vs baseline: 1.5827x; 1.2826x over previous
#include <cuda_runtime.h>
#include <cuda_bf16.h>
#include <math.h>
#include <cstdint>

#define BSZ 512
#define FD  512
#define HD  512
#define ED  8
#define OD  512
#define SK  4   // split-K factor for gating layer 2

// ---------------- scratch (device globals; allocation is forbidden) ----------------
__device__ float d_h2[BSZ * HD];
__device__ float d_g [BSZ * ED];
__device__ float d_T [ED * BSZ * HD];
__device__ float d_part[SK * BSZ * HD];

__device__ __align__(16) __nv_bfloat16 d_xhi[BSZ * FD], d_xlo[BSZ * FD];
__device__ __align__(16) __nv_bfloat16 d_ahi[BSZ * FD], d_alo[BSZ * FD];
__device__ __align__(16) __nv_bfloat16 d_g0hi[HD * FD], d_g0lo[HD * FD];
__device__ __align__(16) __nv_bfloat16 d_g1hi[HD * HD], d_g1lo[HD * HD];
__device__ __align__(16) __nv_bfloat16 d_w0hi[ED * HD * FD], d_w0lo[ED * HD * FD];
__device__ __align__(16) __nv_bfloat16 d_w1hi[ED * HD * HD], d_w1lo[ED * HD * HD];
__device__ __align__(16) __nv_bfloat16 d_w2hi[ED * OD * HD], d_w2lo[ED * OD * HD];

__device__ __forceinline__ float elu1(float v) { return v > 0.f ? v : expm1f(v); }

__device__ __forceinline__ uint32_t smem_u32(const void* p) {
    uint32_t a;
    asm("{ .reg .u64 t; cvta.to.shared.u64 t, %1; cvt.u32.u64 %0, t; }" : "=r"(a) : "l"(p));
    return a;
}

#define CP16(dst, src) \
    asm volatile("cp.async.cg.shared.global [%0], [%1], 16;" :: "r"(dst), "l"(src))

#define LDSM4(r, addr) \
    asm volatile("ldmatrix.sync.aligned.m8n8.x4.shared.b16 {%0,%1,%2,%3}, [%4];" \
                 : "=r"((r)[0]), "=r"((r)[1]), "=r"((r)[2]), "=r"((r)[3]) : "r"(addr))

#define MMA16816(d, a, b0, b1) \
    asm volatile("mma.sync.aligned.m16n8k16.row.col.f32.bf16.bf16.f32 " \
                 "{%0,%1,%2,%3},{%4,%5,%6,%7},{%8,%9},{%0,%1,%2,%3};" \
                 : "+f"((d)[0]), "+f"((d)[1]), "+f"((d)[2]), "+f"((d)[3]) \
                 : "r"((a)[0]), "r"((a)[1]), "r"((a)[2]), "r"((a)[3]), "r"(b0), "r"(b1))

__device__ __forceinline__ uint32_t pack_bf16x2(float a, float b) {
    uint32_t r;
    asm("cvt.rn.bf16x2.f32 %0, %1, %2;" : "=r"(r) : "f"(b), "f"(a));
    return r;
}

// ---------------- split-conversion: fp32 -> (hi, lo) bf16 ----------------
__device__ __forceinline__ void split_one(const float4* in, uint2* hi, uint2* lo, int i) {
    float4 v = in[i];
    float h0 = __bfloat162float(__float2bfloat16(v.x));
    float h1 = __bfloat162float(__float2bfloat16(v.y));
    float h2 = __bfloat162float(__float2bfloat16(v.z));
    float h3 = __bfloat162float(__float2bfloat16(v.w));
    uint2 H, L;
    H.x = pack_bf16x2(h0, h1); H.y = pack_bf16x2(h2, h3);
    L.x = pack_bf16x2(v.x - h0, v.y - h1);
    L.y = pack_bf16x2(v.z - h2, v.w - h3);
    hi[i] = H; lo[i] = L;
}

__global__ void __launch_bounds__(256)
conv_split(const float4* __restrict__ in, uint2* __restrict__ hi, uint2* __restrict__ lo, int n4) {
    int i = blockIdx.x * 256 + threadIdx.x;
    if (i < n4) split_one(in, hi, lo, i);
}

__global__ void __launch_bounds__(256)
conv_split3(const float4* __restrict__ in0, uint2* __restrict__ hi0, uint2* __restrict__ lo0,
            const float4* __restrict__ in1, uint2* __restrict__ hi1, uint2* __restrict__ lo1,
            const float4* __restrict__ in2, uint2* __restrict__ hi2, uint2* __restrict__ lo2)
{
    const int t = blockIdx.x >> 11;
    const int i = (blockIdx.x & 2047) * 256 + threadIdx.x;
    if (t == 0)      split_one(in0, hi0, lo0, i);
    else if (t == 1) split_one(in1, hi1, lo1, i);
    else             split_one(in2, hi2, lo2, i);
}

__global__ void __launch_bounds__(256)
conv_split2(const float4* __restrict__ in0, uint2* __restrict__ hi0, uint2* __restrict__ lo0,
            const float4* __restrict__ in1, uint2* __restrict__ hi1, uint2* __restrict__ lo1)
{
    const int t = blockIdx.x >> 8;
    const int i = (blockIdx.x & 255) * 256 + threadIdx.x;
    if (t == 0) split_one(in0, hi0, lo0, i);
    else        split_one(in1, hi1, lo1, i);
}

// ---------------- fused 3-pass split GEMM (128x128 tile, BK=64, 3-stage) ----------------
// z < nExp: expert path -> C = T + z*strideC, plain fp32 (mode 0).
// z >= nExp (only in merged launch): gating path -> B=gBhi/gBlo, bias=gBias,
//   out split bf16 to gOhi/gOlo (mode 2).
__global__ void __launch_bounds__(256)
tgemm_fused(const __nv_bfloat16* __restrict__ Axhi, const __nv_bfloat16* __restrict__ Axlo,
            const __nv_bfloat16* __restrict__ Bwhi, const __nv_bfloat16* __restrict__ Bwlo,
            float* __restrict__ C, long strideW, long strideC, int nExp,
            const __nv_bfloat16* __restrict__ gBhi, const __nv_bfloat16* __restrict__ gBlo,
            const float* __restrict__ gBias,
            __nv_bfloat16* __restrict__ gOhi, __nv_bfloat16* __restrict__ gOlo)
{
    extern __shared__ __align__(128) char smem[];
    const uint32_t sb = smem_u32(smem);
    const int tid = threadIdx.x;
    const int wid = tid >> 5, lane = tid & 31;
    const int e = blockIdx.z;
    const int bm = blockIdx.y * 128, bn = blockIdx.x * 128;

    const int gating = (e >= nExp);
    const __nv_bfloat16* Bhi_p = gating ? gBhi : Bwhi + (long)e * strideW;
    const __nv_bfloat16* Blo_p = gating ? gBlo : Bwlo + (long)e * strideW;
    C += (long)e * strideC;

    const int lsub = tid >> 3;
    const int lc16 = tid & 7;

    const __nv_bfloat16* tp[4] = { Axhi, Axlo, Bhi_p, Blo_p };
    const int toff[4] = { bm, bm, bn, bn };

    auto load_stage = [&](int kc, int buf) {
        const int k0 = kc << 6;
        const uint32_t base = sb + (uint32_t)buf * 65536u;
        #pragma unroll
        for (int t = 0; t < 4; t++) {
            const __nv_bfloat16* P = tp[t];
            #pragma unroll
            for (int it = 0; it < 4; it++) {
                const int row = it * 32 + lsub;
                const uint32_t dst = base + (uint32_t)t * 16384u
                                   + (uint32_t)(row * 128 + ((lc16 ^ (row & 7)) << 4));
                CP16(dst, P + (long)(toff[t] + row) * 512 + k0 + lc16 * 8);
            }
        }
    };

    const int warpM = wid & 3, warpN = wid >> 2;
    const int arow = warpM * 32 + (lane & 15);
    const uint32_t aswz = (uint32_t)(arow & 7);
    const uint32_t ahalf = (uint32_t)(lane >> 4);
    const int q = lane >> 3;
    const int brow_base = warpN * 64 + ((q >> 1) << 3) + (lane & 7);
    const uint32_t bk = (uint32_t)(q & 1);

    float acc[2][8][4] = {};

    load_stage(0, 0);
    asm volatile("cp.async.commit_group;" ::: "memory");
    load_stage(1, 1);
    asm volatile("cp.async.commit_group;" ::: "memory");

    for (int c = 0; c < 8; c++) {
        if (c < 7) asm volatile("cp.async.wait_group 1;" ::: "memory");
        else       asm volatile("cp.async.wait_group 0;" ::: "memory");
        __syncthreads();
        if (c + 2 < 8) {
            load_stage(c + 2, (c + 2) % 3);
            asm volatile("cp.async.commit_group;" ::: "memory");
        }

        const uint32_t S   = sb + (uint32_t)(c % 3) * 65536u;
        const uint32_t Ahi = S, Alo = S + 16384u, Bhi = S + 32768u, Blo = S + 49152u;

        #pragma unroll
        for (int ks = 0; ks < 4; ks++) {
            const uint32_t achunk = (((uint32_t)(ks << 1) + ahalf) ^ aswz) << 4;
            uint32_t ah[2][4], al[2][4];
            #pragma unroll
            for (int mi = 0; mi < 2; mi++) {
                const uint32_t roff = (uint32_t)((arow + mi * 16) * 128);
                LDSM4(ah[mi], Ahi + roff + achunk);
                LDSM4(al[mi], Alo + roff + achunk);
            }
            uint32_t b[4][4];
            #pragma unroll
            for (int np = 0; np < 4; np++) {
                const int brow = brow_base + np * 16;
                const uint32_t boff = (uint32_t)(brow * 128)
                                    + ((((uint32_t)(ks << 1) + bk) ^ (uint32_t)(brow & 7)) << 4);
                LDSM4(b[np], Bhi + boff);
            }
            #pragma unroll
            for (int mi = 0; mi < 2; mi++)
                #pragma unroll
                for (int ni = 0; ni < 8; ni++) {
                    MMA16816(acc[mi][ni], ah[mi], b[ni >> 1][(ni & 1) * 2],
                             b[ni >> 1][(ni & 1) * 2 + 1]);
                    MMA16816(acc[mi][ni], al[mi], b[ni >> 1][(ni & 1) * 2],
                             b[ni >> 1][(ni & 1) * 2 + 1]);
                }
            #pragma unroll
            for (int np = 0; np < 4; np++) {
                const int brow = brow_base + np * 16;
                const uint32_t boff = (uint32_t)(brow * 128)
                                    + ((((uint32_t)(ks << 1) + bk) ^ (uint32_t)(brow & 7)) << 4);
                LDSM4(b[np], Blo + boff);
            }
            #pragma unroll
            for (int mi = 0; mi < 2; mi++)
                #pragma unroll
                for (int ni = 0; ni < 8; ni++)
                    MMA16816(acc[mi][ni], ah[mi], b[ni >> 1][(ni & 1) * 2],
                             b[ni >> 1][(ni & 1) * 2 + 1]);
        }
        __syncthreads();
    }

    const int gr = lane >> 2, gc = (lane & 3) * 2;
    #pragma unroll
    for (int mi = 0; mi < 2; mi++) {
        const int row0 = bm + warpM * 32 + mi * 16 + gr;
        #pragma unroll
        for (int ni = 0; ni < 8; ni++) {
            const int col = bn + warpN * 64 + ni * 8 + gc;
            float v0 = acc[mi][ni][0], v1 = acc[mi][ni][1];
            float v2 = acc[mi][ni][2], v3 = acc[mi][ni][3];
            if (gating) {
                const float b0 = gBias[col], b1 = gBias[col + 1];
                v0 = elu1(v0 + b0); v1 = elu1(v1 + b1);
                v2 = elu1(v2 + b0); v3 = elu1(v3 + b1);
                float h0f = __bfloat162float(__float2bfloat16(v0));
                float h1f = __bfloat162float(__float2bfloat16(v1));
                float h2f = __bfloat162float(__float2bfloat16(v2));
                float h3f = __bfloat162float(__float2bfloat16(v3));
                *(uint32_t*)&gOhi[(long)row0 * 512 + col]       = pack_bf16x2(h0f, h1f);
                *(uint32_t*)&gOlo[(long)row0 * 512 + col]       = pack_bf16x2(v0 - h0f, v1 - h1f);
                *(uint32_t*)&gOhi[(long)(row0 + 8) * 512 + col] = pack_bf16x2(h2f, h3f);
                *(uint32_t*)&gOlo[(long)(row0 + 8) * 512 + col] = pack_bf16x2(v2 - h2f, v3 - h3f);
            } else {
                *(float2*)&C[(long)row0 * 512 + col]       = make_float2(v0, v1);
                *(float2*)&C[(long)(row0 + 8) * 512 + col] = make_float2(v2, v3);
            }
        }
    }
}

// ---------------- split-K 3-pass GEMM for gating L2 ----------------
// grid (4,4,SK); CTA z handles K range [z*128, z*128+128) (2 BK-chunks), writes
// raw fp32 partial to part + z*BSZ*HD.
__global__ void __launch_bounds__(256)
tgemm_splitk(const __nv_bfloat16* __restrict__ Axhi, const __nv_bfloat16* __restrict__ Axlo,
             const __nv_bfloat16* __restrict__ Bhi_p, const __nv_bfloat16* __restrict__ Blo_p,
             float* __restrict__ part)
{
    extern __shared__ __align__(128) char smem[];
    const uint32_t sb = smem_u32(smem);
    const int tid = threadIdx.x;
    const int wid = tid >> 5, lane = tid & 31;
    const int z = blockIdx.z;
    const int bm = blockIdx.y * 128, bn = blockIdx.x * 128;
    const int kc0 = z * 2;   // first BK-chunk index
    float* C = part + (long)z * BSZ * HD;

    const int lsub = tid >> 3;
    const int lc16 = tid & 7;

    const __nv_bfloat16* tp[4] = { Axhi, Axlo, Bhi_p, Blo_p };
    const int toff[4] = { bm, bm, bn, bn };

    auto load_stage = [&](int kc, int buf) {
        const int k0 = kc << 6;
        const uint32_t base = sb + (uint32_t)buf * 65536u;
        #pragma unroll
        for (int t = 0; t < 4; t++) {
            const __nv_bfloat16* P = tp[t];
            #pragma unroll
            for (int it = 0; it < 4; it++) {
                const int row = it * 32 + lsub;
                const uint32_t dst = base + (uint32_t)t * 16384u
                                   + (uint32_t)(row * 128 + ((lc16 ^ (row & 7)) << 4));
                CP16(dst, P + (long)(toff[t] + row) * 512 + k0 + lc16 * 8);
            }
        }
    };

    const int warpM = wid & 3, warpN = wid >> 2;
    const int arow = warpM * 32 + (lane & 15);
    const uint32_t aswz = (uint32_t)(arow & 7);
    const uint32_t ahalf = (uint32_t)(lane >> 4);
    const int q = lane >> 3;
    const int brow_base = warpN * 64 + ((q >> 1) << 3) + (lane & 7);
    const uint32_t bk = (uint32_t)(q & 1);

    float acc[2][8][4] = {};

    load_stage(kc0, 0);
    asm volatile("cp.async.commit_group;" ::: "memory");
    load_stage(kc0 + 1, 1);
    asm volatile("cp.async.commit_group;" ::: "memory");

    #pragma unroll
    for (int c = 0; c < 2; c++) {
        if (c == 0) asm volatile("cp.async.wait_group 1;" ::: "memory");
        else        asm volatile("cp.async.wait_group 0;" ::: "memory");
        __syncthreads();

        const uint32_t S   = sb + (uint32_t)c * 65536u;
        const uint32_t Ahi = S, Alo = S + 16384u, Bhi = S + 32768u, Blo = S + 49152u;

        #pragma unroll
        for (int ks = 0; ks < 4; ks++) {
            const uint32_t achunk = (((uint32_t)(ks << 1) + ahalf) ^ aswz) << 4;
            uint32_t ah[2][4], al[2][4];
            #pragma unroll
            for (int mi = 0; mi < 2; mi++) {
                const uint32_t roff = (uint32_t)((arow + mi * 16) * 128);
                LDSM4(ah[mi], Ahi + roff + achunk);
                LDSM4(al[mi], Alo + roff + achunk);
            }
            uint32_t b[4][4];
            #pragma unroll
            for (int np = 0; np < 4; np++) {
                const int brow = brow_base + np * 16;
                const uint32_t boff = (uint32_t)(brow * 128)
                                    + ((((uint32_t)(ks << 1) + bk) ^ (uint32_t)(brow & 7)) << 4);
                LDSM4(b[np], Bhi + boff);
            }
            #pragma unroll
            for (int mi = 0; mi < 2; mi++)
                #pragma unroll
                for (int ni = 0; ni < 8; ni++) {
                    MMA16816(acc[mi][ni], ah[mi], b[ni >> 1][(ni & 1) * 2],
                             b[ni >> 1][(ni & 1) * 2 + 1]);
                    MMA16816(acc[mi][ni], al[mi], b[ni >> 1][(ni & 1) * 2],
                             b[ni >> 1][(ni & 1) * 2 + 1]);
                }
            #pragma unroll
            for (int np = 0; np < 4; np++) {
                const int brow = brow_base + np * 16;
                const uint32_t boff = (uint32_t)(brow * 128)
                                    + ((((uint32_t)(ks << 1) + bk) ^ (uint32_t)(brow & 7)) << 4);
                LDSM4(b[np], Blo + boff);
            }
            #pragma unroll
            for (int mi = 0; mi < 2; mi++)
                #pragma unroll
                for (int ni = 0; ni < 8; ni++)
                    MMA16816(acc[mi][ni], ah[mi], b[ni >> 1][(ni & 1) * 2],
                             b[ni >> 1][(ni & 1) * 2 + 1]);
        }
        __syncthreads();
    }

    const int gr = lane >> 2, gc = (lane & 3) * 2;
    #pragma unroll
    for (int mi = 0; mi < 2; mi++) {
        const int row0 = bm + warpM * 32 + mi * 16 + gr;
        #pragma unroll
        for (int ni = 0; ni < 8; ni++) {
            const int col = bn + warpN * 64 + ni * 8 + gc;
            *(float2*)&C[(long)row0 * 512 + col]       = make_float2(acc[mi][ni][0], acc[mi][ni][1]);
            *(float2*)&C[(long)(row0 + 8) * 512 + col] = make_float2(acc[mi][ni][2], acc[mi][ni][3]);
        }
    }
}

// ---------------- split-K reduce: h2 = elu(sum_z part[z] + bias) ----------------
__global__ void __launch_bounds__(256)
reduce_gate(const float4* __restrict__ part, const float* __restrict__ bias,
            float4* __restrict__ h2)
{
    const int i4 = blockIdx.x * 256 + threadIdx.x;   // 65536
    const int col = (i4 << 2) & 511;
    float4 s = part[i4];
    #pragma unroll
    for (int z = 1; z < SK; z++) {
        const float4 p = part[z * (BSZ * HD / 4) + i4];
        s.x += p.x; s.y += p.y; s.z += p.z; s.w += p.w;
    }
    s.x = elu1(s.x + bias[col]);     s.y = elu1(s.y + bias[col + 1]);
    s.z = elu1(s.z + bias[col + 2]); s.w = elu1(s.w + bias[col + 3]);
    h2[i4] = s;
}

// ---------------- gating softmax ----------------
__global__ void __launch_bounds__(256)
gate_kernel(const float* __restrict__ h, const float* __restrict__ w2,
            const float* __restrict__ b2, float* __restrict__ g)
{
    __shared__ float s[512];
    __shared__ float lg[8];
    const int b = blockIdx.x, tid = threadIdx.x;
    for (int i = tid; i < 512; i += 256) s[i] = h[(long)b * 512 + i];
    __syncthreads();

    const int w = tid >> 5, lane = tid & 31;
    float sum = 0.f;
    for (int i = lane; i < 512; i += 32) sum += s[i] * w2[(long)w * 512 + i];
    #pragma unroll
    for (int o = 16; o > 0; o >>= 1) sum += __shfl_xor_sync(0xffffffffu, sum, o);
    if (lane == 0) lg[w] = sum + b2[w];
    __syncthreads();

    if (tid == 0) {
        float mx = lg[0];
        #pragma unroll
        for (int i = 1; i < 8; i++) mx = fmaxf(mx, lg[i]);
        float ex[8], se = 0.f;
        #pragma unroll
        for (int i = 0; i < 8; i++) { ex[i] = expf(lg[i] - mx); se += ex[i]; }
        float inv = 1.f / se;
        #pragma unroll
        for (int i = 0; i < 8; i++) g[(long)b * 8 + i] = ex[i] * inv;
    }
}

// ---------------- gated blend (float4) ----------------
__global__ void __launch_bounds__(256)
blend_kernel(const float4* __restrict__ T4, const float* __restrict__ g,
             const float4* __restrict__ beta4, float* __restrict__ out,
             __nv_bfloat16* __restrict__ Ohi, __nv_bfloat16* __restrict__ Olo, int mode)
{
    const int i4 = blockIdx.x * 256 + threadIdx.x;
    const int base = i4 << 2;
    const int b = base >> 9, h4 = (base & 511) >> 2;
    float4 sum = make_float4(0.f, 0.f, 0.f, 0.f);
    #pragma unroll
    for (int e = 0; e < 8; e++) {
        const float ge = g[b * 8 + e];
        const float4 t = T4[(e << 16) + i4];
        const float4 be = beta4[(e << 7) + h4];
        sum.x += ge * (t.x + be.x); sum.y += ge * (t.y + be.y);
        sum.z += ge * (t.z + be.z); sum.w += ge * (t.w + be.w);
    }
    if (mode == 0) {
        ((float4*)out)[i4] = sum;
    } else {
        sum.x = elu1(sum.x); sum.y = elu1(sum.y); sum.z = elu1(sum.z); sum.w = elu1(sum.w);
        float h0 = __bfloat162float(__float2bfloat16(sum.x));
        float h1 = __bfloat162float(__float2bfloat16(sum.y));
        float h2 = __bfloat162float(__float2bfloat16(sum.z));
        float h3 = __bfloat162float(__float2bfloat16(sum.w));
        uint2 H, L;
        H.x = pack_bf16x2(h0, h1); H.y = pack_bf16x2(h2, h3);
        L.x = pack_bf16x2(sum.x - h0, sum.y - h1);
        L.y = pack_bf16x2(sum.z - h2, sum.w - h3);
        ((uint2*)Ohi)[i4] = H;
        ((uint2*)Olo)[i4] = L;
    }
}

// ---------------- launch ----------------
extern "C" void kernel_launch(void* const* d_in, const int* in_sizes, int n_in,
                              void* d_out, int out_size)
{
    const float* x      = (const float*)d_in[0];
    const float* gw0    = (const float*)d_in[1];
    const float* gb0    = (const float*)d_in[2];
    const float* gw1    = (const float*)d_in[3];
    const float* gb1    = (const float*)d_in[4];
    const float* gw2    = (const float*)d_in[5];
    const float* gb2    = (const float*)d_in[6];
    const float* alpha0 = (const float*)d_in[7];
    const float* beta0  = (const float*)d_in[8];
    const float* alpha1 = (const float*)d_in[9];
    const float* beta1  = (const float*)d_in[10];
    const float* alpha2 = (const float*)d_in[11];
    const float* beta2  = (const float*)d_in[12];
    float* out = (float*)d_out;

    float *h2, *gp, *T, *part;
    cudaGetSymbolAddress((void**)&h2, d_h2);
    cudaGetSymbolAddress((void**)&gp, d_g);
    cudaGetSymbolAddress((void**)&T,  d_T);
    cudaGetSymbolAddress((void**)&part, d_part);

    __nv_bfloat16 *xhi, *xlo, *ahi, *alo, *g0hi, *g0lo, *g1hi, *g1lo;
    __nv_bfloat16 *w0hi, *w0lo, *w1hi, *w1lo, *w2hi, *w2lo;
    cudaGetSymbolAddress((void**)&xhi,  d_xhi);  cudaGetSymbolAddress((void**)&xlo,  d_xlo);
    cudaGetSymbolAddress((void**)&ahi,  d_ahi);  cudaGetSymbolAddress((void**)&alo,  d_alo);
    cudaGetSymbolAddress((void**)&g0hi, d_g0hi); cudaGetSymbolAddress((void**)&g0lo, d_g0lo);
    cudaGetSymbolAddress((void**)&g1hi, d_g1hi); cudaGetSymbolAddress((void**)&g1lo, d_g1lo);
    cudaGetSymbolAddress((void**)&w0hi, d_w0hi); cudaGetSymbolAddress((void**)&w0lo, d_w0lo);
    cudaGetSymbolAddress((void**)&w1hi, d_w1hi); cudaGetSymbolAddress((void**)&w1lo, d_w1lo);
    cudaGetSymbolAddress((void**)&w2hi, d_w2hi); cudaGetSymbolAddress((void**)&w2lo, d_w2lo);

    const int SMEM_SZ = 3 * 65536;
    cudaFuncSetAttribute(tgemm_fused,  cudaFuncAttributeMaxDynamicSharedMemorySize, SMEM_SZ);
    cudaFuncSetAttribute(tgemm_splitk, cudaFuncAttributeMaxDynamicSharedMemorySize, SMEM_SZ);

    const int NSMALL4 = (512 * 512) / 4;
    const long sW = 512L * 512, sC = 512L * 512;
    dim3 gMerged(4, 4, 9), g8(4, 4, 8), gSK(4, 4, SK);
    const int BLEND_B = (BSZ * HD / 4) / 256;

    // conversions
    conv_split<<<NSMALL4 / 256, 256>>>((const float4*)x, (uint2*)xhi, (uint2*)xlo, NSMALL4);
    conv_split2<<<2 * 256, 256>>>((const float4*)gw0, (uint2*)g0hi, (uint2*)g0lo,
                                  (const float4*)gw1, (uint2*)g1hi, (uint2*)g1lo);
    conv_split3<<<3 * 2048, 256>>>((const float4*)alpha0, (uint2*)w0hi, (uint2*)w0lo,
                                   (const float4*)alpha1, (uint2*)w1hi, (uint2*)w1lo,
                                   (const float4*)alpha2, (uint2*)w2hi, (uint2*)w2lo);

    // merged launch: expert layer-1 GEMM (z 0..7) + gating layer-1 (z 8)
    tgemm_fused<<<gMerged, 256, SMEM_SZ>>>(xhi, xlo, w0hi, w0lo, T, sW, sC, 8,
                                           g0hi, g0lo, gb0, ahi, alo);

    // gating layer-2 via split-K, then reduce + softmax
    tgemm_splitk<<<gSK, 256, SMEM_SZ>>>(ahi, alo, g1hi, g1lo, part);
    reduce_gate<<<NSMALL4 / 256, 256>>>((const float4*)part, gb1, (float4*)h2);
    gate_kernel<<<BSZ, 256>>>(h2, gw2, gb2, gp);

    // expert layer 1 blend (overwrites ahi/alo with expert activations)
    blend_kernel<<<BLEND_B, 256>>>((const float4*)T, gp, (const float4*)beta0, nullptr, ahi, alo, 1);

    // expert layer 2
    tgemm_fused<<<g8, 256, SMEM_SZ>>>(ahi, alo, w1hi, w1lo, T, sW, sC, 8,
                                      nullptr, nullptr, nullptr, nullptr, nullptr);
    blend_kernel<<<BLEND_B, 256>>>((const float4*)T, gp, (const float4*)beta1, nullptr, ahi, alo, 1);

    // expert layer 3 (final: fp32, no activation)
    tgemm_fused<<<g8, 256, SMEM_SZ>>>(ahi, alo, w2hi, w2lo, T, sW, sC, 8,
                                      nullptr, nullptr, nullptr, nullptr, nullptr);
    blend_kernel<<<BLEND_B, 256>>>((const float4*)T, gp, (const float4*)beta2, out, nullptr, nullptr, 0);
}

// round 9
// speedup vs baseline: 2.0554x; 1.2987x over previous
#include <cuda_runtime.h>
#include <cuda_fp16.h>
#include <math.h>
#include <cstdint>

#define BSZ 512
#define FD  512
#define HD  512
#define ED  8
#define OD  512

// ---------------- scratch (device globals; allocation is forbidden) ----------------
__device__ float d_h2[BSZ * HD];
__device__ float d_g [BSZ * ED];
__device__ float d_T [ED * BSZ * HD];

__device__ __align__(16) __half d_xhi[BSZ * FD], d_xlo[BSZ * FD];
__device__ __align__(16) __half d_ahi[BSZ * FD], d_alo[BSZ * FD];
__device__ __align__(16) __half d_g0h[HD * FD];
__device__ __align__(16) __half d_g1h[HD * HD];
__device__ __align__(16) __half d_w0h[ED * HD * FD];
__device__ __align__(16) __half d_w1h[ED * HD * HD];
__device__ __align__(16) __half d_w2h[ED * OD * HD];

__device__ __forceinline__ float elu1(float v) { return v > 0.f ? v : expm1f(v); }

__device__ __forceinline__ uint32_t smem_u32(const void* p) {
    uint32_t a;
    asm("{ .reg .u64 t; cvta.to.shared.u64 t, %1; cvt.u32.u64 %0, t; }" : "=r"(a) : "l"(p));
    return a;
}

#define CP16(dst, src) \
    asm volatile("cp.async.cg.shared.global [%0], [%1], 16;" :: "r"(dst), "l"(src))

#define LDSM4(r, addr) \
    asm volatile("ldmatrix.sync.aligned.m8n8.x4.shared.b16 {%0,%1,%2,%3}, [%4];" \
                 : "=r"((r)[0]), "=r"((r)[1]), "=r"((r)[2]), "=r"((r)[3]) : "r"(addr))

#define MMA16816F(d, a, b0, b1) \
    asm volatile("mma.sync.aligned.m16n8k16.row.col.f32.f16.f16.f32 " \
                 "{%0,%1,%2,%3},{%4,%5,%6,%7},{%8,%9},{%0,%1,%2,%3};" \
                 : "+f"((d)[0]), "+f"((d)[1]), "+f"((d)[2]), "+f"((d)[3]) \
                 : "r"((a)[0]), "r"((a)[1]), "r"((a)[2]), "r"((a)[3]), "r"(b0), "r"(b1))

__device__ __forceinline__ uint32_t pack_h2(float a, float b) {
    __half2 h = __floats2half2_rn(a, b);
    return *(uint32_t*)&h;
}

// ---------------- conversions ----------------
__global__ void __launch_bounds__(256)
conv_splitH(const float4* __restrict__ in, uint2* __restrict__ hi, uint2* __restrict__ lo, int n4) {
    int i = blockIdx.x * 256 + threadIdx.x;
    if (i >= n4) return;
    float4 v = in[i];
    float h0 = __half2float(__float2half_rn(v.x));
    float h1 = __half2float(__float2half_rn(v.y));
    float h2 = __half2float(__float2half_rn(v.z));
    float h3 = __half2float(__float2half_rn(v.w));
    uint2 H, L;
    H.x = pack_h2(h0, h1); H.y = pack_h2(h2, h3);
    L.x = pack_h2(v.x - h0, v.y - h1);
    L.y = pack_h2(v.z - h2, v.w - h3);
    hi[i] = H; lo[i] = L;
}

__device__ __forceinline__ void half_one(const float4* in, uint2* hi, int i) {
    float4 v = in[i];
    uint2 H;
    H.x = pack_h2(v.x, v.y); H.y = pack_h2(v.z, v.w);
    hi[i] = H;
}

__global__ void __launch_bounds__(256)
conv_half2(const float4* __restrict__ in0, uint2* __restrict__ hi0,
           const float4* __restrict__ in1, uint2* __restrict__ hi1)
{
    const int t = blockIdx.x >> 8;
    const int i = (blockIdx.x & 255) * 256 + threadIdx.x;
    if (t == 0) half_one(in0, hi0, i);
    else        half_one(in1, hi1, i);
}

__global__ void __launch_bounds__(256)
conv_half3(const float4* __restrict__ in0, uint2* __restrict__ hi0,
           const float4* __restrict__ in1, uint2* __restrict__ hi1,
           const float4* __restrict__ in2, uint2* __restrict__ hi2)
{
    const int t = blockIdx.x >> 11;
    const int i = (blockIdx.x & 2047) * 256 + threadIdx.x;
    if (t == 0)      half_one(in0, hi0, i);
    else if (t == 1) half_one(in1, hi1, i);
    else             half_one(in2, hi2, i);
}

// ---------------- fp16 2-pass split GEMM, 64x64 tile, BK=64, 2-stage ----------------
// acc = Ahi·B^T + Alo·B^T over K=512. Stage = [Ahi 8K][Alo 8K][B 8K] = 24KB; 48KB total
// -> 4 CTAs/SM. 128 threads, warp tile 32x32 (2x2 warps).
// z < nExp: expert path -> C += z*strideC, raw fp32. z >= nExp: gating path -> B=gB,
//   epilogue gEpi: 1 = bias+elu fp32 to C; 2 = bias+elu split fp16 to gOhi/gOlo.
__global__ void __launch_bounds__(128, 4)
tgemm(const __half* __restrict__ Axhi, const __half* __restrict__ Axlo,
      const __half* __restrict__ Bw, float* __restrict__ C,
      long strideW, long strideC, int nExp,
      const __half* __restrict__ gB, const float* __restrict__ gBias, int gEpi,
      __half* __restrict__ gOhi, __half* __restrict__ gOlo)
{
    extern __shared__ __align__(128) char smem[];
    const uint32_t sb = smem_u32(smem);
    const int tid = threadIdx.x;
    const int wid = tid >> 5, lane = tid & 31;
    const int e = blockIdx.z;
    const int bm = blockIdx.y * 64, bn = blockIdx.x * 64;

    const int gating = (e >= nExp);
    const __half* Bp = gating ? gB : Bw + (long)e * strideW;
    C += (long)e * strideC;

    const int lsub = tid >> 3;   // 0..15
    const int lc16 = tid & 7;

    const __half* tp[3] = { Axhi, Axlo, Bp };
    const int toff[3] = { bm, bm, bn };

    auto load_stage = [&](int kc, int buf) {
        const int k0 = kc << 6;
        const uint32_t base = sb + (uint32_t)buf * 24576u;
        #pragma unroll
        for (int t = 0; t < 3; t++) {
            const __half* P = tp[t];
            #pragma unroll
            for (int it = 0; it < 4; it++) {
                const int row = it * 16 + lsub;
                const uint32_t dst = base + (uint32_t)t * 8192u
                                   + (uint32_t)(row * 128 + ((lc16 ^ (row & 7)) << 4));
                CP16(dst, P + (long)(toff[t] + row) * 512 + k0 + lc16 * 8);
            }
        }
    };

    const int warpM = wid & 1, warpN = wid >> 1;
    const int arow = warpM * 32 + (lane & 15);
    const uint32_t aswz = (uint32_t)(arow & 7);
    const uint32_t ahalf = (uint32_t)(lane >> 4);
    const int q = lane >> 3;
    const int brow_base = warpN * 32 + ((q >> 1) << 3) + (lane & 7);
    const uint32_t bk = (uint32_t)(q & 1);

    float acc[2][4][4] = {};

    load_stage(0, 0);
    asm volatile("cp.async.commit_group;" ::: "memory");

    for (int c = 0; c < 8; c++) {
        if (c + 1 < 8) {
            load_stage(c + 1, (c + 1) & 1);
            asm volatile("cp.async.commit_group;" ::: "memory");
            asm volatile("cp.async.wait_group 1;" ::: "memory");
        } else {
            asm volatile("cp.async.wait_group 0;" ::: "memory");
        }
        __syncthreads();

        const uint32_t S   = sb + (uint32_t)(c & 1) * 24576u;
        const uint32_t Ahi = S, Alo = S + 8192u, Bh = S + 16384u;

        #pragma unroll
        for (int ks = 0; ks < 4; ks++) {
            const uint32_t achunk = (((uint32_t)(ks << 1) + ahalf) ^ aswz) << 4;
            uint32_t ah[2][4], al[2][4];
            #pragma unroll
            for (int mi = 0; mi < 2; mi++) {
                const uint32_t roff = (uint32_t)((arow + mi * 16) * 128);
                LDSM4(ah[mi], Ahi + roff + achunk);
                LDSM4(al[mi], Alo + roff + achunk);
            }
            uint32_t b[2][4];
            #pragma unroll
            for (int np = 0; np < 2; np++) {
                const int brow = brow_base + np * 16;
                const uint32_t boff = (uint32_t)(brow * 128)
                                    + ((((uint32_t)(ks << 1) + bk) ^ (uint32_t)(brow & 7)) << 4);
                LDSM4(b[np], Bh + boff);
            }
            #pragma unroll
            for (int mi = 0; mi < 2; mi++)
                #pragma unroll
                for (int ni = 0; ni < 4; ni++) {
                    MMA16816F(acc[mi][ni], ah[mi], b[ni >> 1][(ni & 1) * 2],
                              b[ni >> 1][(ni & 1) * 2 + 1]);
                    MMA16816F(acc[mi][ni], al[mi], b[ni >> 1][(ni & 1) * 2],
                              b[ni >> 1][(ni & 1) * 2 + 1]);
                }
        }
        __syncthreads();
    }

    const int gr = lane >> 2, gc = (lane & 3) * 2;
    #pragma unroll
    for (int mi = 0; mi < 2; mi++) {
        const int row0 = bm + warpM * 32 + mi * 16 + gr;
        #pragma unroll
        for (int ni = 0; ni < 4; ni++) {
            const int col = bn + warpN * 32 + ni * 8 + gc;
            float v0 = acc[mi][ni][0], v1 = acc[mi][ni][1];
            float v2 = acc[mi][ni][2], v3 = acc[mi][ni][3];
            if (gating) {
                const float b0 = gBias[col], b1 = gBias[col + 1];
                v0 = elu1(v0 + b0); v1 = elu1(v1 + b1);
                v2 = elu1(v2 + b0); v3 = elu1(v3 + b1);
                if (gEpi == 2) {
                    float h0f = __half2float(__float2half_rn(v0));
                    float h1f = __half2float(__float2half_rn(v1));
                    float h2f = __half2float(__float2half_rn(v2));
                    float h3f = __half2float(__float2half_rn(v3));
                    *(uint32_t*)&gOhi[(long)row0 * 512 + col]       = pack_h2(h0f, h1f);
                    *(uint32_t*)&gOlo[(long)row0 * 512 + col]       = pack_h2(v0 - h0f, v1 - h1f);
                    *(uint32_t*)&gOhi[(long)(row0 + 8) * 512 + col] = pack_h2(h2f, h3f);
                    *(uint32_t*)&gOlo[(long)(row0 + 8) * 512 + col] = pack_h2(v2 - h2f, v3 - h3f);
                    continue;
                }
            }
            *(float2*)&C[(long)row0 * 512 + col]       = make_float2(v0, v1);
            *(float2*)&C[(long)(row0 + 8) * 512 + col] = make_float2(v2, v3);
        }
    }
}

// ---------------- gating softmax ----------------
__global__ void __launch_bounds__(256)
gate_kernel(const float* __restrict__ h, const float* __restrict__ w2,
            const float* __restrict__ b2, float* __restrict__ g)
{
    __shared__ float s[512];
    __shared__ float lg[8];
    const int b = blockIdx.x, tid = threadIdx.x;
    for (int i = tid; i < 512; i += 256) s[i] = h[(long)b * 512 + i];
    __syncthreads();

    const int w = tid >> 5, lane = tid & 31;
    float sum = 0.f;
    for (int i = lane; i < 512; i += 32) sum += s[i] * w2[(long)w * 512 + i];
    #pragma unroll
    for (int o = 16; o > 0; o >>= 1) sum += __shfl_xor_sync(0xffffffffu, sum, o);
    if (lane == 0) lg[w] = sum + b2[w];
    __syncthreads();

    if (tid == 0) {
        float mx = lg[0];
        #pragma unroll
        for (int i = 1; i < 8; i++) mx = fmaxf(mx, lg[i]);
        float ex[8], se = 0.f;
        #pragma unroll
        for (int i = 0; i < 8; i++) { ex[i] = expf(lg[i] - mx); se += ex[i]; }
        float inv = 1.f / se;
        #pragma unroll
        for (int i = 0; i < 8; i++) g[(long)b * 8 + i] = ex[i] * inv;
    }
}

// ---------------- gated blend (float4) ----------------
// mode 0: out fp32 (final). mode 1: elu then split fp16 hi/lo.
__global__ void __launch_bounds__(256)
blend_kernel(const float4* __restrict__ T4, const float* __restrict__ g,
             const float4* __restrict__ beta4, float* __restrict__ out,
             __half* __restrict__ Ohi, __half* __restrict__ Olo, int mode)
{
    const int i4 = blockIdx.x * 256 + threadIdx.x;
    const int base = i4 << 2;
    const int b = base >> 9, h4 = (base & 511) >> 2;
    float4 sum = make_float4(0.f, 0.f, 0.f, 0.f);
    #pragma unroll
    for (int e = 0; e < 8; e++) {
        const float ge = g[b * 8 + e];
        const float4 t = T4[(e << 16) + i4];
        const float4 be = beta4[(e << 7) + h4];
        sum.x += ge * (t.x + be.x); sum.y += ge * (t.y + be.y);
        sum.z += ge * (t.z + be.z); sum.w += ge * (t.w + be.w);
    }
    if (mode == 0) {
        ((float4*)out)[i4] = sum;
    } else {
        sum.x = elu1(sum.x); sum.y = elu1(sum.y); sum.z = elu1(sum.z); sum.w = elu1(sum.w);
        float h0 = __half2float(__float2half_rn(sum.x));
        float h1 = __half2float(__float2half_rn(sum.y));
        float h2 = __half2float(__float2half_rn(sum.z));
        float h3 = __half2float(__float2half_rn(sum.w));
        uint2 H, L;
        H.x = pack_h2(h0, h1); H.y = pack_h2(h2, h3);
        L.x = pack_h2(sum.x - h0, sum.y - h1);
        L.y = pack_h2(sum.z - h2, sum.w - h3);
        ((uint2*)Ohi)[i4] = H;
        ((uint2*)Olo)[i4] = L;
    }
}

// ---------------- launch ----------------
extern "C" void kernel_launch(void* const* d_in, const int* in_sizes, int n_in,
                              void* d_out, int out_size)
{
    const float* x      = (const float*)d_in[0];
    const float* gw0    = (const float*)d_in[1];
    const float* gb0    = (const float*)d_in[2];
    const float* gw1    = (const float*)d_in[3];
    const float* gb1    = (const float*)d_in[4];
    const float* gw2    = (const float*)d_in[5];
    const float* gb2    = (const float*)d_in[6];
    const float* alpha0 = (const float*)d_in[7];
    const float* beta0  = (const float*)d_in[8];
    const float* alpha1 = (const float*)d_in[9];
    const float* beta1  = (const float*)d_in[10];
    const float* alpha2 = (const float*)d_in[11];
    const float* beta2  = (const float*)d_in[12];
    float* out = (float*)d_out;

    float *h2, *gp, *T;
    cudaGetSymbolAddress((void**)&h2, d_h2);
    cudaGetSymbolAddress((void**)&gp, d_g);
    cudaGetSymbolAddress((void**)&T,  d_T);

    __half *xhi, *xlo, *ahi, *alo, *g0h, *g1h, *w0h, *w1h, *w2h;
    cudaGetSymbolAddress((void**)&xhi, d_xhi); cudaGetSymbolAddress((void**)&xlo, d_xlo);
    cudaGetSymbolAddress((void**)&ahi, d_ahi); cudaGetSymbolAddress((void**)&alo, d_alo);
    cudaGetSymbolAddress((void**)&g0h, d_g0h); cudaGetSymbolAddress((void**)&g1h, d_g1h);
    cudaGetSymbolAddress((void**)&w0h, d_w0h); cudaGetSymbolAddress((void**)&w1h, d_w1h);
    cudaGetSymbolAddress((void**)&w2h, d_w2h);

    const int SMEM_SZ = 2 * 24576;   // 48KB -> 4 CTAs/SM
    cudaFuncSetAttribute(tgemm, cudaFuncAttributeMaxDynamicSharedMemorySize, SMEM_SZ);

    const int NSMALL4 = (512 * 512) / 4;
    const long sW = 512L * 512, sC = 512L * 512;
    dim3 gMerged(8, 8, 9), g8(8, 8, 8), gGate(8, 8, 1);
    const int BLEND_B = (BSZ * HD / 4) / 256;

    // conversions (x split fp16; weights single fp16, merged launches)
    conv_splitH<<<NSMALL4 / 256, 256>>>((const float4*)x, (uint2*)xhi, (uint2*)xlo, NSMALL4);
    conv_half2<<<2 * 256, 256>>>((const float4*)gw0, (uint2*)g0h,
                                 (const float4*)gw1, (uint2*)g1h);
    conv_half3<<<3 * 2048, 256>>>((const float4*)alpha0, (uint2*)w0h,
                                  (const float4*)alpha1, (uint2*)w1h,
                                  (const float4*)alpha2, (uint2*)w2h);

    // merged: expert layer-1 (z 0..7) + gating layer-1 (z 8, split-fp16 out)
    tgemm<<<gMerged, 128, SMEM_SZ>>>(xhi, xlo, w0h, T, sW, sC, 8,
                                     g0h, gb0, 2, ahi, alo);

    // gating layer-2 (64 CTAs, bias+elu fp32 -> h2), then softmax
    tgemm<<<gGate, 128, SMEM_SZ>>>(ahi, alo, nullptr, h2, 0, 0, 0,
                                   g1h, gb1, 1, nullptr, nullptr);
    gate_kernel<<<BSZ, 256>>>(h2, gw2, gb2, gp);

    // expert layer 1 blend (overwrites ahi/alo)
    blend_kernel<<<BLEND_B, 256>>>((const float4*)T, gp, (const float4*)beta0, nullptr, ahi, alo, 1);

    // expert layer 2
    tgemm<<<g8, 128, SMEM_SZ>>>(ahi, alo, w1h, T, sW, sC, 8,
                                nullptr, nullptr, 0, nullptr, nullptr);
    blend_kernel<<<BLEND_B, 256>>>((const float4*)T, gp, (const float4*)beta1, nullptr, ahi, alo, 1);

    // expert layer 3 (final: fp32, no activation)
    tgemm<<<g8, 128, SMEM_SZ>>>(ahi, alo, w2h, T, sW, sC, 8,
                                nullptr, nullptr, 0, nullptr, nullptr);
    blend_kernel<<<BLEND_B, 256>>>((const float4*)T, gp, (const float4*)beta2, out, nullptr, nullptr, 0);
}

// round 10
// speedup vs baseline: 2.0789x; 1.0115x over previous
#include <cuda_runtime.h>
#include <cuda_fp16.h>
#include <math.h>
#include <cstdint>

#define BSZ 512
#define FD  512
#define HD  512
#define ED  8
#define OD  512
#define SK  4
#define WSTRIDE 262144L   // 512*512

// ---------------- scratch ----------------
__device__ float d_h2[BSZ * HD];
__device__ float d_g [BSZ * ED];
__device__ float d_T [ED * BSZ * HD];          // fp32 T (layer 3); fp16 T aliases front half
__device__ float d_part[SK * BSZ * HD];

__device__ __align__(16) __half d_xhi[BSZ * FD], d_xlo[BSZ * FD];
__device__ __align__(16) __half d_ahi[BSZ * FD], d_alo[BSZ * FD];
__device__ __align__(16) __half d_g0h[HD * FD];
__device__ __align__(16) __half d_g1h[HD * HD];
__device__ __align__(16) __half d_w0h[ED * HD * FD];
__device__ __align__(16) __half d_w1h[ED * HD * HD];
__device__ __align__(16) __half d_w2h[ED * OD * HD];

__device__ __forceinline__ float elu1(float v) { return v > 0.f ? v : expm1f(v); }

__device__ __forceinline__ uint32_t smem_u32(const void* p) {
    uint32_t a;
    asm("{ .reg .u64 t; cvta.to.shared.u64 t, %1; cvt.u32.u64 %0, t; }" : "=r"(a) : "l"(p));
    return a;
}

#define CP16(dst, src) \
    asm volatile("cp.async.cg.shared.global [%0], [%1], 16;" :: "r"(dst), "l"(src))

#define LDSM4(r, addr) \
    asm volatile("ldmatrix.sync.aligned.m8n8.x4.shared.b16 {%0,%1,%2,%3}, [%4];" \
                 : "=r"((r)[0]), "=r"((r)[1]), "=r"((r)[2]), "=r"((r)[3]) : "r"(addr))

#define MMA16816F(d, a, b0, b1) \
    asm volatile("mma.sync.aligned.m16n8k16.row.col.f32.f16.f16.f32 " \
                 "{%0,%1,%2,%3},{%4,%5,%6,%7},{%8,%9},{%0,%1,%2,%3};" \
                 : "+f"((d)[0]), "+f"((d)[1]), "+f"((d)[2]), "+f"((d)[3]) \
                 : "r"((a)[0]), "r"((a)[1]), "r"((a)[2]), "r"((a)[3]), "r"(b0), "r"(b1))

__device__ __forceinline__ uint32_t pack_h2(float a, float b) {
    __half2 h = __floats2half2_rn(a, b);
    return *(uint32_t*)&h;
}

// ---------------- conversions ----------------
__device__ __forceinline__ void split_oneH(const float4* in, uint2* hi, uint2* lo, int i) {
    float4 v = in[i];
    float h0 = __half2float(__float2half_rn(v.x));
    float h1 = __half2float(__float2half_rn(v.y));
    float h2 = __half2float(__float2half_rn(v.z));
    float h3 = __half2float(__float2half_rn(v.w));
    uint2 H, L;
    H.x = pack_h2(h0, h1); H.y = pack_h2(h2, h3);
    L.x = pack_h2(v.x - h0, v.y - h1);
    L.y = pack_h2(v.z - h2, v.w - h3);
    hi[i] = H; lo[i] = L;
}
__device__ __forceinline__ void half_one(const float4* in, uint2* hi, int i) {
    float4 v = in[i];
    uint2 H;
    H.x = pack_h2(v.x, v.y); H.y = pack_h2(v.z, v.w);
    hi[i] = H;
}

// front: x-split (256 blk), gw0 (256), gw1 (256), w0 (2048) = 2816 blocks
__global__ void __launch_bounds__(256)
conv_front(const float4* __restrict__ x, uint2* __restrict__ xhi, uint2* __restrict__ xlo,
           const float4* __restrict__ gw0, uint2* __restrict__ g0h,
           const float4* __restrict__ gw1, uint2* __restrict__ g1h,
           const float4* __restrict__ a0, uint2* __restrict__ w0h)
{
    const int b = blockIdx.x;
    if (b < 256)       split_oneH(x, xhi, xlo, b * 256 + threadIdx.x);
    else if (b < 512)  half_one(gw0, g0h, (b - 256) * 256 + threadIdx.x);
    else if (b < 768)  half_one(gw1, g1h, (b - 512) * 256 + threadIdx.x);
    else               half_one(a0,  w0h, (b - 768) * 256 + threadIdx.x);
}

// side stream: w1 (2048) + w2 (2048)
__global__ void __launch_bounds__(256)
conv_w12(const float4* __restrict__ a1, uint2* __restrict__ w1h,
         const float4* __restrict__ a2, uint2* __restrict__ w2h)
{
    const int b = blockIdx.x;
    if (b < 2048) half_one(a1, w1h, b * 256 + threadIdx.x);
    else          half_one(a2, w2h, (b - 2048) * 256 + threadIdx.x);
}

// ---------------- fp16 2-pass split GEMM, 64x64 tile, BK=64, 2-stage ----------------
// z < nExp: expert path (out fp16 Ch if outHalf else fp32 Cf, offset z*WSTRIDE).
// z == nExp (merged launch only): gating L1 -> bias+elu, split fp16 to gOhi/gOlo.
__global__ void __launch_bounds__(128, 4)
tgemm(const __half* __restrict__ Axhi, const __half* __restrict__ Axlo,
      const __half* __restrict__ Bw, float* __restrict__ Cf, __half* __restrict__ Ch,
      int nExp, int outHalf,
      const __half* __restrict__ gB, const float* __restrict__ gBias,
      __half* __restrict__ gOhi, __half* __restrict__ gOlo)
{
    extern __shared__ __align__(128) char smem[];
    const uint32_t sb = smem_u32(smem);
    const int tid = threadIdx.x;
    const int wid = tid >> 5, lane = tid & 31;
    const int e = blockIdx.z;
    const int bm = blockIdx.y * 64, bn = blockIdx.x * 64;

    const int gating = (e >= nExp);
    const __half* Bp = gating ? gB : Bw + (long)e * WSTRIDE;
    Cf += (long)e * WSTRIDE;
    Ch += (long)e * WSTRIDE;

    const int lsub = tid >> 3;
    const int lc16 = tid & 7;

    const __half* tp[3] = { Axhi, Axlo, Bp };
    const int toff[3] = { bm, bm, bn };

    auto load_stage = [&](int kc, int buf) {
        const int k0 = kc << 6;
        const uint32_t base = sb + (uint32_t)buf * 24576u;
        #pragma unroll
        for (int t = 0; t < 3; t++) {
            const __half* P = tp[t];
            #pragma unroll
            for (int it = 0; it < 4; it++) {
                const int row = it * 16 + lsub;
                const uint32_t dst = base + (uint32_t)t * 8192u
                                   + (uint32_t)(row * 128 + ((lc16 ^ (row & 7)) << 4));
                CP16(dst, P + (long)(toff[t] + row) * 512 + k0 + lc16 * 8);
            }
        }
    };

    const int warpM = wid & 1, warpN = wid >> 1;
    const int arow = warpM * 32 + (lane & 15);
    const uint32_t aswz = (uint32_t)(arow & 7);
    const uint32_t ahalf = (uint32_t)(lane >> 4);
    const int q = lane >> 3;
    const int brow_base = warpN * 32 + ((q >> 1) << 3) + (lane & 7);
    const uint32_t bk = (uint32_t)(q & 1);

    float acc[2][4][4] = {};

    load_stage(0, 0);
    asm volatile("cp.async.commit_group;" ::: "memory");

    for (int c = 0; c < 8; c++) {
        if (c + 1 < 8) {
            load_stage(c + 1, (c + 1) & 1);
            asm volatile("cp.async.commit_group;" ::: "memory");
            asm volatile("cp.async.wait_group 1;" ::: "memory");
        } else {
            asm volatile("cp.async.wait_group 0;" ::: "memory");
        }
        __syncthreads();

        const uint32_t S   = sb + (uint32_t)(c & 1) * 24576u;
        const uint32_t Ahi = S, Alo = S + 8192u, Bh = S + 16384u;

        #pragma unroll
        for (int ks = 0; ks < 4; ks++) {
            const uint32_t achunk = (((uint32_t)(ks << 1) + ahalf) ^ aswz) << 4;
            uint32_t ah[2][4], al[2][4];
            #pragma unroll
            for (int mi = 0; mi < 2; mi++) {
                const uint32_t roff = (uint32_t)((arow + mi * 16) * 128);
                LDSM4(ah[mi], Ahi + roff + achunk);
                LDSM4(al[mi], Alo + roff + achunk);
            }
            uint32_t b[2][4];
            #pragma unroll
            for (int np = 0; np < 2; np++) {
                const int brow = brow_base + np * 16;
                const uint32_t boff = (uint32_t)(brow * 128)
                                    + ((((uint32_t)(ks << 1) + bk) ^ (uint32_t)(brow & 7)) << 4);
                LDSM4(b[np], Bh + boff);
            }
            #pragma unroll
            for (int mi = 0; mi < 2; mi++)
                #pragma unroll
                for (int ni = 0; ni < 4; ni++) {
                    MMA16816F(acc[mi][ni], ah[mi], b[ni >> 1][(ni & 1) * 2],
                              b[ni >> 1][(ni & 1) * 2 + 1]);
                    MMA16816F(acc[mi][ni], al[mi], b[ni >> 1][(ni & 1) * 2],
                              b[ni >> 1][(ni & 1) * 2 + 1]);
                }
        }
        __syncthreads();
    }

    const int gr = lane >> 2, gc = (lane & 3) * 2;
    #pragma unroll
    for (int mi = 0; mi < 2; mi++) {
        const int row0 = bm + warpM * 32 + mi * 16 + gr;
        #pragma unroll
        for (int ni = 0; ni < 4; ni++) {
            const int col = bn + warpN * 32 + ni * 8 + gc;
            float v0 = acc[mi][ni][0], v1 = acc[mi][ni][1];
            float v2 = acc[mi][ni][2], v3 = acc[mi][ni][3];
            if (gating) {
                const float b0 = gBias[col], b1 = gBias[col + 1];
                v0 = elu1(v0 + b0); v1 = elu1(v1 + b1);
                v2 = elu1(v2 + b0); v3 = elu1(v3 + b1);
                float h0f = __half2float(__float2half_rn(v0));
                float h1f = __half2float(__float2half_rn(v1));
                float h2f = __half2float(__float2half_rn(v2));
                float h3f = __half2float(__float2half_rn(v3));
                *(uint32_t*)&gOhi[(long)row0 * 512 + col]       = pack_h2(h0f, h1f);
                *(uint32_t*)&gOlo[(long)row0 * 512 + col]       = pack_h2(v0 - h0f, v1 - h1f);
                *(uint32_t*)&gOhi[(long)(row0 + 8) * 512 + col] = pack_h2(h2f, h3f);
                *(uint32_t*)&gOlo[(long)(row0 + 8) * 512 + col] = pack_h2(v2 - h2f, v3 - h3f);
            } else if (outHalf) {
                *(uint32_t*)&Ch[(long)row0 * 512 + col]       = pack_h2(v0, v1);
                *(uint32_t*)&Ch[(long)(row0 + 8) * 512 + col] = pack_h2(v2, v3);
            } else {
                *(float2*)&Cf[(long)row0 * 512 + col]       = make_float2(v0, v1);
                *(float2*)&Cf[(long)(row0 + 8) * 512 + col] = make_float2(v2, v3);
            }
        }
    }
}

// ---------------- split-K gating L2: grid (8,8,SK), z covers chunks 2z..2z+1 ----------------
__global__ void __launch_bounds__(128, 4)
tgemm_sk(const __half* __restrict__ Axhi, const __half* __restrict__ Axlo,
         const __half* __restrict__ Bp, float* __restrict__ part)
{
    extern __shared__ __align__(128) char smem[];
    const uint32_t sb = smem_u32(smem);
    const int tid = threadIdx.x;
    const int wid = tid >> 5, lane = tid & 31;
    const int z = blockIdx.z;
    const int bm = blockIdx.y * 64, bn = blockIdx.x * 64;
    float* C = part + (long)z * BSZ * HD;

    const int lsub = tid >> 3;
    const int lc16 = tid & 7;

    const __half* tp[3] = { Axhi, Axlo, Bp };
    const int toff[3] = { bm, bm, bn };

    auto load_stage = [&](int kc, int buf) {
        const int k0 = kc << 6;
        const uint32_t base = sb + (uint32_t)buf * 24576u;
        #pragma unroll
        for (int t = 0; t < 3; t++) {
            const __half* P = tp[t];
            #pragma unroll
            for (int it = 0; it < 4; it++) {
                const int row = it * 16 + lsub;
                const uint32_t dst = base + (uint32_t)t * 8192u
                                   + (uint32_t)(row * 128 + ((lc16 ^ (row & 7)) << 4));
                CP16(dst, P + (long)(toff[t] + row) * 512 + k0 + lc16 * 8);
            }
        }
    };

    const int warpM = wid & 1, warpN = wid >> 1;
    const int arow = warpM * 32 + (lane & 15);
    const uint32_t aswz = (uint32_t)(arow & 7);
    const uint32_t ahalf = (uint32_t)(lane >> 4);
    const int q = lane >> 3;
    const int brow_base = warpN * 32 + ((q >> 1) << 3) + (lane & 7);
    const uint32_t bk = (uint32_t)(q & 1);

    float acc[2][4][4] = {};

    load_stage(z * 2, 0);
    asm volatile("cp.async.commit_group;" ::: "memory");
    load_stage(z * 2 + 1, 1);
    asm volatile("cp.async.commit_group;" ::: "memory");

    #pragma unroll
    for (int c = 0; c < 2; c++) {
        if (c == 0) asm volatile("cp.async.wait_group 1;" ::: "memory");
        else        asm volatile("cp.async.wait_group 0;" ::: "memory");
        __syncthreads();

        const uint32_t S   = sb + (uint32_t)c * 24576u;
        const uint32_t Ahi = S, Alo = S + 8192u, Bh = S + 16384u;

        #pragma unroll
        for (int ks = 0; ks < 4; ks++) {
            const uint32_t achunk = (((uint32_t)(ks << 1) + ahalf) ^ aswz) << 4;
            uint32_t ah[2][4], al[2][4];
            #pragma unroll
            for (int mi = 0; mi < 2; mi++) {
                const uint32_t roff = (uint32_t)((arow + mi * 16) * 128);
                LDSM4(ah[mi], Ahi + roff + achunk);
                LDSM4(al[mi], Alo + roff + achunk);
            }
            uint32_t b[2][4];
            #pragma unroll
            for (int np = 0; np < 2; np++) {
                const int brow = brow_base + np * 16;
                const uint32_t boff = (uint32_t)(brow * 128)
                                    + ((((uint32_t)(ks << 1) + bk) ^ (uint32_t)(brow & 7)) << 4);
                LDSM4(b[np], Bh + boff);
            }
            #pragma unroll
            for (int mi = 0; mi < 2; mi++)
                #pragma unroll
                for (int ni = 0; ni < 4; ni++) {
                    MMA16816F(acc[mi][ni], ah[mi], b[ni >> 1][(ni & 1) * 2],
                              b[ni >> 1][(ni & 1) * 2 + 1]);
                    MMA16816F(acc[mi][ni], al[mi], b[ni >> 1][(ni & 1) * 2],
                              b[ni >> 1][(ni & 1) * 2 + 1]);
                }
        }
        __syncthreads();
    }

    const int gr = lane >> 2, gc = (lane & 3) * 2;
    #pragma unroll
    for (int mi = 0; mi < 2; mi++) {
        const int row0 = bm + warpM * 32 + mi * 16 + gr;
        #pragma unroll
        for (int ni = 0; ni < 4; ni++) {
            const int col = bn + warpN * 32 + ni * 8 + gc;
            *(float2*)&C[(long)row0 * 512 + col]       = make_float2(acc[mi][ni][0], acc[mi][ni][1]);
            *(float2*)&C[(long)(row0 + 8) * 512 + col] = make_float2(acc[mi][ni][2], acc[mi][ni][3]);
        }
    }
}

__global__ void __launch_bounds__(256)
reduce_gate(const float4* __restrict__ part, const float* __restrict__ bias,
            float4* __restrict__ h2)
{
    const int i4 = blockIdx.x * 256 + threadIdx.x;
    const int col = (i4 << 2) & 511;
    float4 s = part[i4];
    #pragma unroll
    for (int z = 1; z < SK; z++) {
        const float4 p = part[z * (BSZ * HD / 4) + i4];
        s.x += p.x; s.y += p.y; s.z += p.z; s.w += p.w;
    }
    s.x = elu1(s.x + bias[col]);     s.y = elu1(s.y + bias[col + 1]);
    s.z = elu1(s.z + bias[col + 2]); s.w = elu1(s.w + bias[col + 3]);
    h2[i4] = s;
}

// ---------------- gating softmax ----------------
__global__ void __launch_bounds__(256)
gate_kernel(const float* __restrict__ h, const float* __restrict__ w2,
            const float* __restrict__ b2, float* __restrict__ g)
{
    __shared__ float s[512];
    __shared__ float lg[8];
    const int b = blockIdx.x, tid = threadIdx.x;
    for (int i = tid; i < 512; i += 256) s[i] = h[(long)b * 512 + i];
    __syncthreads();

    const int w = tid >> 5, lane = tid & 31;
    float sum = 0.f;
    for (int i = lane; i < 512; i += 32) sum += s[i] * w2[(long)w * 512 + i];
    #pragma unroll
    for (int o = 16; o > 0; o >>= 1) sum += __shfl_xor_sync(0xffffffffu, sum, o);
    if (lane == 0) lg[w] = sum + b2[w];
    __syncthreads();

    if (tid == 0) {
        float mx = lg[0];
        #pragma unroll
        for (int i = 1; i < 8; i++) mx = fmaxf(mx, lg[i]);
        float ex[8], se = 0.f;
        #pragma unroll
        for (int i = 0; i < 8; i++) { ex[i] = expf(lg[i] - mx); se += ex[i]; }
        float inv = 1.f / se;
        #pragma unroll
        for (int i = 0; i < 8; i++) g[(long)b * 8 + i] = ex[i] * inv;
    }
}

// ---------------- blends ----------------
// fp16-T blend, split fp16 output (layers 1, 2)
__global__ void __launch_bounds__(256)
blend_half(const uint2* __restrict__ Th, const float* __restrict__ g,
           const float4* __restrict__ beta4,
           __half* __restrict__ Ohi, __half* __restrict__ Olo)
{
    const int i4 = blockIdx.x * 256 + threadIdx.x;
    const int base = i4 << 2;
    const int b = base >> 9, h4 = (base & 511) >> 2;
    float4 sum = make_float4(0.f, 0.f, 0.f, 0.f);
    #pragma unroll
    for (int e = 0; e < 8; e++) {
        const float ge = g[b * 8 + e];
        const uint2 U = Th[(e << 16) + i4];
        const float2 f0 = __half22float2(*(const __half2*)&U.x);
        const float2 f1 = __half22float2(*(const __half2*)&U.y);
        const float4 be = beta4[(e << 7) + h4];
        sum.x += ge * (f0.x + be.x); sum.y += ge * (f0.y + be.y);
        sum.z += ge * (f1.x + be.z); sum.w += ge * (f1.y + be.w);
    }
    sum.x = elu1(sum.x); sum.y = elu1(sum.y); sum.z = elu1(sum.z); sum.w = elu1(sum.w);
    float h0 = __half2float(__float2half_rn(sum.x));
    float h1 = __half2float(__float2half_rn(sum.y));
    float h2 = __half2float(__float2half_rn(sum.z));
    float h3 = __half2float(__float2half_rn(sum.w));
    uint2 H, L;
    H.x = pack_h2(h0, h1); H.y = pack_h2(h2, h3);
    L.x = pack_h2(sum.x - h0, sum.y - h1);
    L.y = pack_h2(sum.z - h2, sum.w - h3);
    ((uint2*)Ohi)[i4] = H;
    ((uint2*)Olo)[i4] = L;
}

// fp32-T final blend (layer 3)
__global__ void __launch_bounds__(256)
blend_final(const float4* __restrict__ T4, const float* __restrict__ g,
            const float4* __restrict__ beta4, float* __restrict__ out)
{
    const int i4 = blockIdx.x * 256 + threadIdx.x;
    const int base = i4 << 2;
    const int b = base >> 9, h4 = (base & 511) >> 2;
    float4 sum = make_float4(0.f, 0.f, 0.f, 0.f);
    #pragma unroll
    for (int e = 0; e < 8; e++) {
        const float ge = g[b * 8 + e];
        const float4 t = T4[(e << 16) + i4];
        const float4 be = beta4[(e << 7) + h4];
        sum.x += ge * (t.x + be.x); sum.y += ge * (t.y + be.y);
        sum.z += ge * (t.z + be.z); sum.w += ge * (t.w + be.w);
    }
    ((float4*)out)[i4] = sum;
}

// ---------------- launch ----------------
extern "C" void kernel_launch(void* const* d_in, const int* in_sizes, int n_in,
                              void* d_out, int out_size)
{
    const float* x      = (const float*)d_in[0];
    const float* gw0    = (const float*)d_in[1];
    const float* gb0    = (const float*)d_in[2];
    const float* gw1    = (const float*)d_in[3];
    const float* gb1    = (const float*)d_in[4];
    const float* gw2    = (const float*)d_in[5];
    const float* gb2    = (const float*)d_in[6];
    const float* alpha0 = (const float*)d_in[7];
    const float* beta0  = (const float*)d_in[8];
    const float* alpha1 = (const float*)d_in[9];
    const float* beta1  = (const float*)d_in[10];
    const float* alpha2 = (const float*)d_in[11];
    const float* beta2  = (const float*)d_in[12];
    float* out = (float*)d_out;

    float *h2, *gp, *T, *part;
    cudaGetSymbolAddress((void**)&h2, d_h2);
    cudaGetSymbolAddress((void**)&gp, d_g);
    cudaGetSymbolAddress((void**)&T,  d_T);
    cudaGetSymbolAddress((void**)&part, d_part);
    __half* Th = (__half*)T;   // fp16 T aliases the same scratch

    __half *xhi, *xlo, *ahi, *alo, *g0h, *g1h, *w0h, *w1h, *w2h;
    cudaGetSymbolAddress((void**)&xhi, d_xhi); cudaGetSymbolAddress((void**)&xlo, d_xlo);
    cudaGetSymbolAddress((void**)&ahi, d_ahi); cudaGetSymbolAddress((void**)&alo, d_alo);
    cudaGetSymbolAddress((void**)&g0h, d_g0h); cudaGetSymbolAddress((void**)&g1h, d_g1h);
    cudaGetSymbolAddress((void**)&w0h, d_w0h); cudaGetSymbolAddress((void**)&w1h, d_w1h);
    cudaGetSymbolAddress((void**)&w2h, d_w2h);

    const int SMEM_SZ = 2 * 24576;
    cudaFuncSetAttribute(tgemm,    cudaFuncAttributeMaxDynamicSharedMemorySize, SMEM_SZ);
    cudaFuncSetAttribute(tgemm_sk, cudaFuncAttributeMaxDynamicSharedMemorySize, SMEM_SZ);

    dim3 gMerged(8, 8, 9), g8(8, 8, 8), gSK(8, 8, SK);
    const int BLEND_B = (BSZ * HD / 4) / 256;
    const int NSMALL4 = (512 * 512) / 4;

    // side stream for w1/w2 conversion (overlaps merged GEMM + gate chain)
    cudaStream_t s2;
    cudaStreamCreate(&s2);
    cudaEvent_t eFork, eJoin;
    cudaEventCreateWithFlags(&eFork, cudaEventDisableTiming);
    cudaEventCreateWithFlags(&eJoin, cudaEventDisableTiming);

    cudaEventRecord(eFork, 0);
    cudaStreamWaitEvent(s2, eFork, 0);
    conv_w12<<<4096, 256, 0, s2>>>((const float4*)alpha1, (uint2*)w1h,
                                   (const float4*)alpha2, (uint2*)w2h);
    cudaEventRecord(eJoin, s2);

    // front conversions (x split, gw0, gw1, w0)
    conv_front<<<2816, 256>>>((const float4*)x, (uint2*)xhi, (uint2*)xlo,
                              (const float4*)gw0, (uint2*)g0h,
                              (const float4*)gw1, (uint2*)g1h,
                              (const float4*)alpha0, (uint2*)w0h);

    // merged: expert layer-1 (z 0..7, T fp16) + gating layer-1 (z 8, split out)
    tgemm<<<gMerged, 128, SMEM_SZ>>>(xhi, xlo, w0h, T, Th, 8, 1,
                                     g0h, gb0, ahi, alo);

    // gating layer-2 split-K + reduce + softmax
    tgemm_sk<<<gSK, 128, SMEM_SZ>>>(ahi, alo, g1h, part);
    reduce_gate<<<NSMALL4 / 256, 256>>>((const float4*)part, gb1, (float4*)h2);
    gate_kernel<<<BSZ, 256>>>(h2, gw2, gb2, gp);

    // expert layer 1 blend (T fp16 -> split fp16 activations)
    blend_half<<<BLEND_B, 256>>>((const uint2*)Th, gp, (const float4*)beta0, ahi, alo);

    // join w1/w2 conversion before layer-2 GEMM
    cudaStreamWaitEvent(0, eJoin, 0);

    // expert layer 2 (T fp16)
    tgemm<<<g8, 128, SMEM_SZ>>>(ahi, alo, w1h, T, Th, 8, 1,
                                nullptr, nullptr, nullptr, nullptr);
    blend_half<<<BLEND_B, 256>>>((const uint2*)Th, gp, (const float4*)beta1, ahi, alo);

    // expert layer 3 (T fp32) + final blend
    tgemm<<<g8, 128, SMEM_SZ>>>(ahi, alo, w2h, T, Th, 8, 0,
                                nullptr, nullptr, nullptr, nullptr);
    blend_final<<<BLEND_B, 256>>>((const float4*)T, gp, (const float4*)beta2, out);
}

// round 11
// speedup vs baseline: 2.1148x; 1.0173x over previous
#include <cuda_runtime.h>
#include <cuda_fp16.h>
#include <math.h>
#include <cstdint>

#define BSZ 512
#define FD  512
#define HD  512
#define ED  8
#define OD  512
#define SK  2
#define WSTRIDE 262144L   // 512*512

// ---------------- scratch ----------------
__device__ float d_h2[BSZ * HD];
__device__ float d_g [BSZ * ED];
__device__ float d_T [ED * BSZ * HD];          // fp32 T (layer 3); fp16 T aliases
__device__ float d_part[SK * BSZ * HD];

__device__ __align__(16) __half d_xhi[BSZ * FD], d_xlo[BSZ * FD];
__device__ __align__(16) __half d_ahi[BSZ * FD], d_alo[BSZ * FD];
__device__ __align__(16) __half d_g0h[HD * FD];
__device__ __align__(16) __half d_g1h[HD * HD];
__device__ __align__(16) __half d_w0h[ED * HD * FD];
__device__ __align__(16) __half d_w1h[ED * HD * HD];
__device__ __align__(16) __half d_w2h[ED * OD * HD];

__device__ __forceinline__ float elu1(float v) { return v > 0.f ? v : expm1f(v); }

__device__ __forceinline__ uint32_t smem_u32(const void* p) {
    uint32_t a;
    asm("{ .reg .u64 t; cvta.to.shared.u64 t, %1; cvt.u32.u64 %0, t; }" : "=r"(a) : "l"(p));
    return a;
}

#define CP16(dst, src) \
    asm volatile("cp.async.cg.shared.global [%0], [%1], 16;" :: "r"(dst), "l"(src))

#define LDSM4(r, addr) \
    asm volatile("ldmatrix.sync.aligned.m8n8.x4.shared.b16 {%0,%1,%2,%3}, [%4];" \
                 : "=r"((r)[0]), "=r"((r)[1]), "=r"((r)[2]), "=r"((r)[3]) : "r"(addr))

#define MMA16816F(d, a, b0, b1) \
    asm volatile("mma.sync.aligned.m16n8k16.row.col.f32.f16.f16.f32 " \
                 "{%0,%1,%2,%3},{%4,%5,%6,%7},{%8,%9},{%0,%1,%2,%3};" \
                 : "+f"((d)[0]), "+f"((d)[1]), "+f"((d)[2]), "+f"((d)[3]) \
                 : "r"((a)[0]), "r"((a)[1]), "r"((a)[2]), "r"((a)[3]), "r"(b0), "r"(b1))

__device__ __forceinline__ uint32_t pack_h2(float a, float b) {
    __half2 h = __floats2half2_rn(a, b);
    return *(uint32_t*)&h;
}

// ---------------- conversions ----------------
__device__ __forceinline__ void split_oneH(const float4* in, uint2* hi, uint2* lo, int i) {
    float4 v = in[i];
    float h0 = __half2float(__float2half_rn(v.x));
    float h1 = __half2float(__float2half_rn(v.y));
    float h2 = __half2float(__float2half_rn(v.z));
    float h3 = __half2float(__float2half_rn(v.w));
    uint2 H, L;
    H.x = pack_h2(h0, h1); H.y = pack_h2(h2, h3);
    L.x = pack_h2(v.x - h0, v.y - h1);
    L.y = pack_h2(v.z - h2, v.w - h3);
    hi[i] = H; lo[i] = L;
}
__device__ __forceinline__ void half_one(const float4* in, uint2* hi, int i) {
    float4 v = in[i];
    uint2 H;
    H.x = pack_h2(v.x, v.y); H.y = pack_h2(v.z, v.w);
    hi[i] = H;
}

__global__ void __launch_bounds__(256)
conv_front(const float4* __restrict__ x, uint2* __restrict__ xhi, uint2* __restrict__ xlo,
           const float4* __restrict__ gw0, uint2* __restrict__ g0h,
           const float4* __restrict__ gw1, uint2* __restrict__ g1h,
           const float4* __restrict__ a0, uint2* __restrict__ w0h)
{
    const int b = blockIdx.x;
    if (b < 256)       split_oneH(x, xhi, xlo, b * 256 + threadIdx.x);
    else if (b < 512)  half_one(gw0, g0h, (b - 256) * 256 + threadIdx.x);
    else if (b < 768)  half_one(gw1, g1h, (b - 512) * 256 + threadIdx.x);
    else               half_one(a0,  w0h, (b - 768) * 256 + threadIdx.x);
}

__global__ void __launch_bounds__(256)
conv_w12(const float4* __restrict__ a1, uint2* __restrict__ w1h,
         const float4* __restrict__ a2, uint2* __restrict__ w2h)
{
    const int b = blockIdx.x;
    if (b < 2048) half_one(a1, w1h, b * 256 + threadIdx.x);
    else          half_one(a2, w2h, (b - 2048) * 256 + threadIdx.x);
}

// ======== shared GEMM machinery (64x64 tile, BK=64, 2-stage, reg-pipelined) ========
// Frag load: 6 LDSM for one ks into ping-pong buffer.
#define LOAD_FRAGS(buf, ks)                                                         \
    do {                                                                            \
        const uint32_t achunk = (((uint32_t)((ks) << 1) + ahalf) ^ aswz) << 4;      \
        _Pragma("unroll")                                                           \
        for (int mi = 0; mi < 2; mi++) {                                            \
            const uint32_t roff = (uint32_t)((arow + mi * 16) * 128);               \
            LDSM4(ahf[buf][mi], Ahi + roff + achunk);                               \
            LDSM4(alf[buf][mi], Alo + roff + achunk);                               \
        }                                                                           \
        _Pragma("unroll")                                                           \
        for (int np = 0; np < 2; np++) {                                            \
            const int brow = brow_base + np * 16;                                   \
            const uint32_t boff = (uint32_t)(brow * 128)                            \
                + ((((uint32_t)((ks) << 1) + bk) ^ (uint32_t)(brow & 7)) << 4);     \
            LDSM4(bf[buf][np], Bh + boff);                                          \
        }                                                                           \
    } while (0)

#define DO_MMAS(buf)                                                                \
    do {                                                                            \
        _Pragma("unroll")                                                           \
        for (int mi = 0; mi < 2; mi++)                                              \
            _Pragma("unroll")                                                       \
            for (int ni = 0; ni < 4; ni++) {                                        \
                MMA16816F(acc[mi][ni], ahf[buf][mi], bf[buf][ni >> 1][(ni & 1) * 2],\
                          bf[buf][ni >> 1][(ni & 1) * 2 + 1]);                      \
                MMA16816F(acc[mi][ni], alf[buf][mi], bf[buf][ni >> 1][(ni & 1) * 2],\
                          bf[buf][ni >> 1][(ni & 1) * 2 + 1]);                      \
            }                                                                       \
    } while (0)

// ---------------- main GEMM ----------------
// z < nExp: expert path (out fp16 Ch if outHalf else fp32 Cf, offset z*WSTRIDE).
// z == nExp (merged launch): gating L1 -> bias+elu, split fp16 to gOhi/gOlo.
__global__ void __launch_bounds__(128, 4)
tgemm(const __half* __restrict__ Axhi, const __half* __restrict__ Axlo,
      const __half* __restrict__ Bw, float* __restrict__ Cf, __half* __restrict__ Ch,
      int nExp, int outHalf,
      const __half* __restrict__ gB, const float* __restrict__ gBias,
      __half* __restrict__ gOhi, __half* __restrict__ gOlo)
{
    extern __shared__ __align__(128) char smem[];
    const uint32_t sb = smem_u32(smem);
    const int tid = threadIdx.x;
    const int wid = tid >> 5, lane = tid & 31;
    const int e = blockIdx.z;
    const int bm = blockIdx.y * 64, bn = blockIdx.x * 64;

    const int gating = (e >= nExp);
    const __half* Bp = gating ? gB : Bw + (long)e * WSTRIDE;
    Cf += (long)e * WSTRIDE;
    Ch += (long)e * WSTRIDE;

    const int lsub = tid >> 3;
    const int lc16 = tid & 7;

    const __half* tp[3] = { Axhi, Axlo, Bp };
    const int toff[3] = { bm, bm, bn };

    auto load_stage = [&](int kc, int buf) {
        const int k0 = kc << 6;
        const uint32_t base = sb + (uint32_t)buf * 24576u;
        #pragma unroll
        for (int t = 0; t < 3; t++) {
            const __half* P = tp[t];
            #pragma unroll
            for (int it = 0; it < 4; it++) {
                const int row = it * 16 + lsub;
                const uint32_t dst = base + (uint32_t)t * 8192u
                                   + (uint32_t)(row * 128 + ((lc16 ^ (row & 7)) << 4));
                CP16(dst, P + (long)(toff[t] + row) * 512 + k0 + lc16 * 8);
            }
        }
    };

    const int warpM = wid & 1, warpN = wid >> 1;
    const int arow = warpM * 32 + (lane & 15);
    const uint32_t aswz = (uint32_t)(arow & 7);
    const uint32_t ahalf = (uint32_t)(lane >> 4);
    const int q = lane >> 3;
    const int brow_base = warpN * 32 + ((q >> 1) << 3) + (lane & 7);
    const uint32_t bk = (uint32_t)(q & 1);

    float acc[2][4][4] = {};
    uint32_t ahf[2][2][4], alf[2][2][4], bf[2][2][4];

    load_stage(0, 0);
    asm volatile("cp.async.commit_group;" ::: "memory");

    for (int c = 0; c < 8; c++) {
        if (c + 1 < 8) {
            load_stage(c + 1, (c + 1) & 1);
            asm volatile("cp.async.commit_group;" ::: "memory");
            asm volatile("cp.async.wait_group 1;" ::: "memory");
        } else {
            asm volatile("cp.async.wait_group 0;" ::: "memory");
        }
        __syncthreads();

        const uint32_t S   = sb + (uint32_t)(c & 1) * 24576u;
        const uint32_t Ahi = S, Alo = S + 8192u, Bh = S + 16384u;

        LOAD_FRAGS(0, 0);
        #pragma unroll
        for (int ks = 0; ks < 4; ks++) {
            const int cur = ks & 1;
            if (ks < 3) LOAD_FRAGS(cur ^ 1, ks + 1);
            DO_MMAS(cur);
        }
        __syncthreads();
    }

    const int gr = lane >> 2, gc = (lane & 3) * 2;
    #pragma unroll
    for (int mi = 0; mi < 2; mi++) {
        const int row0 = bm + warpM * 32 + mi * 16 + gr;
        #pragma unroll
        for (int ni = 0; ni < 4; ni++) {
            const int col = bn + warpN * 32 + ni * 8 + gc;
            float v0 = acc[mi][ni][0], v1 = acc[mi][ni][1];
            float v2 = acc[mi][ni][2], v3 = acc[mi][ni][3];
            if (gating) {
                const float b0 = gBias[col], b1 = gBias[col + 1];
                v0 = elu1(v0 + b0); v1 = elu1(v1 + b1);
                v2 = elu1(v2 + b0); v3 = elu1(v3 + b1);
                float h0f = __half2float(__float2half_rn(v0));
                float h1f = __half2float(__float2half_rn(v1));
                float h2f = __half2float(__float2half_rn(v2));
                float h3f = __half2float(__float2half_rn(v3));
                *(uint32_t*)&gOhi[(long)row0 * 512 + col]       = pack_h2(h0f, h1f);
                *(uint32_t*)&gOlo[(long)row0 * 512 + col]       = pack_h2(v0 - h0f, v1 - h1f);
                *(uint32_t*)&gOhi[(long)(row0 + 8) * 512 + col] = pack_h2(h2f, h3f);
                *(uint32_t*)&gOlo[(long)(row0 + 8) * 512 + col] = pack_h2(v2 - h2f, v3 - h3f);
            } else if (outHalf) {
                *(uint32_t*)&Ch[(long)row0 * 512 + col]       = pack_h2(v0, v1);
                *(uint32_t*)&Ch[(long)(row0 + 8) * 512 + col] = pack_h2(v2, v3);
            } else {
                *(float2*)&Cf[(long)row0 * 512 + col]       = make_float2(v0, v1);
                *(float2*)&Cf[(long)(row0 + 8) * 512 + col] = make_float2(v2, v3);
            }
        }
    }
}

// ---------------- split-K gating L2: grid (8,8,SK), z covers 4 chunks ----------------
__global__ void __launch_bounds__(128, 4)
tgemm_sk(const __half* __restrict__ Axhi, const __half* __restrict__ Axlo,
         const __half* __restrict__ Bp, float* __restrict__ part)
{
    extern __shared__ __align__(128) char smem[];
    const uint32_t sb = smem_u32(smem);
    const int tid = threadIdx.x;
    const int wid = tid >> 5, lane = tid & 31;
    const int z = blockIdx.z;
    const int bm = blockIdx.y * 64, bn = blockIdx.x * 64;
    const int kc0 = z * 4;
    float* C = part + (long)z * BSZ * HD;

    const int lsub = tid >> 3;
    const int lc16 = tid & 7;

    const __half* tp[3] = { Axhi, Axlo, Bp };
    const int toff[3] = { bm, bm, bn };

    auto load_stage = [&](int kc, int buf) {
        const int k0 = kc << 6;
        const uint32_t base = sb + (uint32_t)buf * 24576u;
        #pragma unroll
        for (int t = 0; t < 3; t++) {
            const __half* P = tp[t];
            #pragma unroll
            for (int it = 0; it < 4; it++) {
                const int row = it * 16 + lsub;
                const uint32_t dst = base + (uint32_t)t * 8192u
                                   + (uint32_t)(row * 128 + ((lc16 ^ (row & 7)) << 4));
                CP16(dst, P + (long)(toff[t] + row) * 512 + k0 + lc16 * 8);
            }
        }
    };

    const int warpM = wid & 1, warpN = wid >> 1;
    const int arow = warpM * 32 + (lane & 15);
    const uint32_t aswz = (uint32_t)(arow & 7);
    const uint32_t ahalf = (uint32_t)(lane >> 4);
    const int q = lane >> 3;
    const int brow_base = warpN * 32 + ((q >> 1) << 3) + (lane & 7);
    const uint32_t bk = (uint32_t)(q & 1);

    float acc[2][4][4] = {};
    uint32_t ahf[2][2][4], alf[2][2][4], bf[2][2][4];

    load_stage(kc0, 0);
    asm volatile("cp.async.commit_group;" ::: "memory");

    for (int c = 0; c < 4; c++) {
        if (c + 1 < 4) {
            load_stage(kc0 + c + 1, (c + 1) & 1);
            asm volatile("cp.async.commit_group;" ::: "memory");
            asm volatile("cp.async.wait_group 1;" ::: "memory");
        } else {
            asm volatile("cp.async.wait_group 0;" ::: "memory");
        }
        __syncthreads();

        const uint32_t S   = sb + (uint32_t)(c & 1) * 24576u;
        const uint32_t Ahi = S, Alo = S + 8192u, Bh = S + 16384u;

        LOAD_FRAGS(0, 0);
        #pragma unroll
        for (int ks = 0; ks < 4; ks++) {
            const int cur = ks & 1;
            if (ks < 3) LOAD_FRAGS(cur ^ 1, ks + 1);
            DO_MMAS(cur);
        }
        __syncthreads();
    }

    const int gr = lane >> 2, gc = (lane & 3) * 2;
    #pragma unroll
    for (int mi = 0; mi < 2; mi++) {
        const int row0 = bm + warpM * 32 + mi * 16 + gr;
        #pragma unroll
        for (int ni = 0; ni < 4; ni++) {
            const int col = bn + warpN * 32 + ni * 8 + gc;
            *(float2*)&C[(long)row0 * 512 + col]       = make_float2(acc[mi][ni][0], acc[mi][ni][1]);
            *(float2*)&C[(long)(row0 + 8) * 512 + col] = make_float2(acc[mi][ni][2], acc[mi][ni][3]);
        }
    }
}

__global__ void __launch_bounds__(256)
reduce_gate(const float4* __restrict__ part, const float* __restrict__ bias,
            float4* __restrict__ h2)
{
    const int i4 = blockIdx.x * 256 + threadIdx.x;
    const int col = (i4 << 2) & 511;
    float4 s = part[i4];
    #pragma unroll
    for (int z = 1; z < SK; z++) {
        const float4 p = part[z * (BSZ * HD / 4) + i4];
        s.x += p.x; s.y += p.y; s.z += p.z; s.w += p.w;
    }
    s.x = elu1(s.x + bias[col]);     s.y = elu1(s.y + bias[col + 1]);
    s.z = elu1(s.z + bias[col + 2]); s.w = elu1(s.w + bias[col + 3]);
    h2[i4] = s;
}

// ---------------- gating softmax ----------------
__global__ void __launch_bounds__(256)
gate_kernel(const float* __restrict__ h, const float* __restrict__ w2,
            const float* __restrict__ b2, float* __restrict__ g)
{
    __shared__ float s[512];
    __shared__ float lg[8];
    const int b = blockIdx.x, tid = threadIdx.x;
    for (int i = tid; i < 512; i += 256) s[i] = h[(long)b * 512 + i];
    __syncthreads();

    const int w = tid >> 5, lane = tid & 31;
    float sum = 0.f;
    for (int i = lane; i < 512; i += 32) sum += s[i] * w2[(long)w * 512 + i];
    #pragma unroll
    for (int o = 16; o > 0; o >>= 1) sum += __shfl_xor_sync(0xffffffffu, sum, o);
    if (lane == 0) lg[w] = sum + b2[w];
    __syncthreads();

    if (tid == 0) {
        float mx = lg[0];
        #pragma unroll
        for (int i = 1; i < 8; i++) mx = fmaxf(mx, lg[i]);
        float ex[8], se = 0.f;
        #pragma unroll
        for (int i = 0; i < 8; i++) { ex[i] = expf(lg[i] - mx); se += ex[i]; }
        float inv = 1.f / se;
        #pragma unroll
        for (int i = 0; i < 8; i++) g[(long)b * 8 + i] = ex[i] * inv;
    }
}

// ---------------- blends ----------------
__global__ void __launch_bounds__(256)
blend_half(const uint2* __restrict__ Th, const float* __restrict__ g,
           const float4* __restrict__ beta4,
           __half* __restrict__ Ohi, __half* __restrict__ Olo)
{
    const int i4 = blockIdx.x * 256 + threadIdx.x;
    const int base = i4 << 2;
    const int b = base >> 9, h4 = (base & 511) >> 2;
    float4 sum = make_float4(0.f, 0.f, 0.f, 0.f);
    #pragma unroll
    for (int e = 0; e < 8; e++) {
        const float ge = g[b * 8 + e];
        const uint2 U = Th[(e << 16) + i4];
        const float2 f0 = __half22float2(*(const __half2*)&U.x);
        const float2 f1 = __half22float2(*(const __half2*)&U.y);
        const float4 be = beta4[(e << 7) + h4];
        sum.x += ge * (f0.x + be.x); sum.y += ge * (f0.y + be.y);
        sum.z += ge * (f1.x + be.z); sum.w += ge * (f1.y + be.w);
    }
    sum.x = elu1(sum.x); sum.y = elu1(sum.y); sum.z = elu1(sum.z); sum.w = elu1(sum.w);
    float h0 = __half2float(__float2half_rn(sum.x));
    float h1 = __half2float(__float2half_rn(sum.y));
    float h2 = __half2float(__float2half_rn(sum.z));
    float h3 = __half2float(__float2half_rn(sum.w));
    uint2 H, L;
    H.x = pack_h2(h0, h1); H.y = pack_h2(h2, h3);
    L.x = pack_h2(sum.x - h0, sum.y - h1);
    L.y = pack_h2(sum.z - h2, sum.w - h3);
    ((uint2*)Ohi)[i4] = H;
    ((uint2*)Olo)[i4] = L;
}

__global__ void __launch_bounds__(256)
blend_final(const float4* __restrict__ T4, const float* __restrict__ g,
            const float4* __restrict__ beta4, float* __restrict__ out)
{
    const int i4 = blockIdx.x * 256 + threadIdx.x;
    const int base = i4 << 2;
    const int b = base >> 9, h4 = (base & 511) >> 2;
    float4 sum = make_float4(0.f, 0.f, 0.f, 0.f);
    #pragma unroll
    for (int e = 0; e < 8; e++) {
        const float ge = g[b * 8 + e];
        const float4 t = T4[(e << 16) + i4];
        const float4 be = beta4[(e << 7) + h4];
        sum.x += ge * (t.x + be.x); sum.y += ge * (t.y + be.y);
        sum.z += ge * (t.z + be.z); sum.w += ge * (t.w + be.w);
    }
    ((float4*)out)[i4] = sum;
}

// ---------------- launch ----------------
extern "C" void kernel_launch(void* const* d_in, const int* in_sizes, int n_in,
                              void* d_out, int out_size)
{
    const float* x      = (const float*)d_in[0];
    const float* gw0    = (const float*)d_in[1];
    const float* gb0    = (const float*)d_in[2];
    const float* gw1    = (const float*)d_in[3];
    const float* gb1    = (const float*)d_in[4];
    const float* gw2    = (const float*)d_in[5];
    const float* gb2    = (const float*)d_in[6];
    const float* alpha0 = (const float*)d_in[7];
    const float* beta0  = (const float*)d_in[8];
    const float* alpha1 = (const float*)d_in[9];
    const float* beta1  = (const float*)d_in[10];
    const float* alpha2 = (const float*)d_in[11];
    const float* beta2  = (const float*)d_in[12];
    float* out = (float*)d_out;

    float *h2, *gp, *T, *part;
    cudaGetSymbolAddress((void**)&h2, d_h2);
    cudaGetSymbolAddress((void**)&gp, d_g);
    cudaGetSymbolAddress((void**)&T,  d_T);
    cudaGetSymbolAddress((void**)&part, d_part);
    __half* Th = (__half*)T;

    __half *xhi, *xlo, *ahi, *alo, *g0h, *g1h, *w0h, *w1h, *w2h;
    cudaGetSymbolAddress((void**)&xhi, d_xhi); cudaGetSymbolAddress((void**)&xlo, d_xlo);
    cudaGetSymbolAddress((void**)&ahi, d_ahi); cudaGetSymbolAddress((void**)&alo, d_alo);
    cudaGetSymbolAddress((void**)&g0h, d_g0h); cudaGetSymbolAddress((void**)&g1h, d_g1h);
    cudaGetSymbolAddress((void**)&w0h, d_w0h); cudaGetSymbolAddress((void**)&w1h, d_w1h);
    cudaGetSymbolAddress((void**)&w2h, d_w2h);

    const int SMEM_SZ = 2 * 24576;
    cudaFuncSetAttribute(tgemm,    cudaFuncAttributeMaxDynamicSharedMemorySize, SMEM_SZ);
    cudaFuncSetAttribute(tgemm_sk, cudaFuncAttributeMaxDynamicSharedMemorySize, SMEM_SZ);

    dim3 gMerged(8, 8, 9), g8(8, 8, 8), gSK(8, 8, SK);
    const int BLEND_B = (BSZ * HD / 4) / 256;
    const int NSMALL4 = (512 * 512) / 4;

    // side stream for w1/w2 conversion (overlaps merged GEMM + gate chain)
    cudaStream_t s2;
    cudaStreamCreate(&s2);
    cudaEvent_t eFork, eJoin;
    cudaEventCreateWithFlags(&eFork, cudaEventDisableTiming);
    cudaEventCreateWithFlags(&eJoin, cudaEventDisableTiming);

    cudaEventRecord(eFork, 0);
    cudaStreamWaitEvent(s2, eFork, 0);
    conv_w12<<<4096, 256, 0, s2>>>((const float4*)alpha1, (uint2*)w1h,
                                   (const float4*)alpha2, (uint2*)w2h);
    cudaEventRecord(eJoin, s2);

    // front conversions (x split, gw0, gw1, w0)
    conv_front<<<2816, 256>>>((const float4*)x, (uint2*)xhi, (uint2*)xlo,
                              (const float4*)gw0, (uint2*)g0h,
                              (const float4*)gw1, (uint2*)g1h,
                              (const float4*)alpha0, (uint2*)w0h);

    // merged: expert layer-1 (z 0..7, T fp16) + gating layer-1 (z 8, split out)
    tgemm<<<gMerged, 128, SMEM_SZ>>>(xhi, xlo, w0h, T, Th, 8, 1,
                                     g0h, gb0, ahi, alo);

    // gating layer-2 split-K(2) + reduce + softmax
    tgemm_sk<<<gSK, 128, SMEM_SZ>>>(ahi, alo, g1h, part);
    reduce_gate<<<NSMALL4 / 256, 256>>>((const float4*)part, gb1, (float4*)h2);
    gate_kernel<<<BSZ, 256>>>(h2, gw2, gb2, gp);

    // expert layer 1 blend (T fp16 -> split fp16 activations)
    blend_half<<<BLEND_B, 256>>>((const uint2*)Th, gp, (const float4*)beta0, ahi, alo);

    // join w1/w2 conversion before layer-2 GEMM
    cudaStreamWaitEvent(0, eJoin, 0);

    // expert layer 2 (T fp16)
    tgemm<<<g8, 128, SMEM_SZ>>>(ahi, alo, w1h, T, Th, 8, 1,
                                nullptr, nullptr, nullptr, nullptr);
    blend_half<<<BLEND_B, 256>>>((const uint2*)Th, gp, (const float4*)beta1, ahi, alo);

    // expert layer 3 (T fp32) + final blend
    tgemm<<<g8, 128, SMEM_SZ>>>(ahi, alo, w2h, T, Th, 8, 0,
                                nullptr, nullptr, nullptr, nullptr);
    blend_final<<<BLEND_B, 256>>>((const float4*)T, gp, (const float4*)beta2, out);
}

// round 12
// speedup vs baseline: 2.5013x; 1.1827x over previous
#include <cuda_runtime.h>
#include <cuda_fp16.h>
#include <math.h>
#include <cstdint>

#define BSZ 512
#define FD  512
#define HD  512
#define ED  8
#define OD  512
#define WSTRIDE 262144L   // 512*512

// ---------------- scratch ----------------
__device__ float d_h2[BSZ * HD];
__device__ float d_g [BSZ * ED];
__device__ float d_T [ED * BSZ * HD];          // fp32 T (layer 3); fp16 T aliases

__device__ __align__(16) __half d_xh[BSZ * FD];
__device__ __align__(16) __half d_ah[BSZ * FD];
__device__ __align__(16) __half d_g0h[HD * FD];
__device__ __align__(16) __half d_g1h[HD * HD];
__device__ __align__(16) __half d_w0h[ED * HD * FD];
__device__ __align__(16) __half d_w1h[ED * HD * HD];
__device__ __align__(16) __half d_w2h[ED * OD * HD];

__device__ __forceinline__ float elu1(float v) { return v > 0.f ? v : expm1f(v); }

__device__ __forceinline__ uint32_t smem_u32(const void* p) {
    uint32_t a;
    asm("{ .reg .u64 t; cvta.to.shared.u64 t, %1; cvt.u32.u64 %0, t; }" : "=r"(a) : "l"(p));
    return a;
}

#define CP16(dst, src) \
    asm volatile("cp.async.cg.shared.global [%0], [%1], 16;" :: "r"(dst), "l"(src))

#define LDSM4(r, addr) \
    asm volatile("ldmatrix.sync.aligned.m8n8.x4.shared.b16 {%0,%1,%2,%3}, [%4];" \
                 : "=r"((r)[0]), "=r"((r)[1]), "=r"((r)[2]), "=r"((r)[3]) : "r"(addr))

#define MMA16816F(d, a, b0, b1) \
    asm volatile("mma.sync.aligned.m16n8k16.row.col.f32.f16.f16.f32 " \
                 "{%0,%1,%2,%3},{%4,%5,%6,%7},{%8,%9},{%0,%1,%2,%3};" \
                 : "+f"((d)[0]), "+f"((d)[1]), "+f"((d)[2]), "+f"((d)[3]) \
                 : "r"((a)[0]), "r"((a)[1]), "r"((a)[2]), "r"((a)[3]), "r"(b0), "r"(b1))

__device__ __forceinline__ uint32_t pack_h2(float a, float b) {
    __half2 h = __floats2half2_rn(a, b);
    return *(uint32_t*)&h;
}

// ---------------- conversions ----------------
__device__ __forceinline__ void half_one(const float4* in, uint2* hi, int i) {
    float4 v = in[i];
    uint2 H;
    H.x = pack_h2(v.x, v.y); H.y = pack_h2(v.z, v.w);
    hi[i] = H;
}

// front: x (256 blk), gw0 (256), gw1 (256), w0 (2048) = 2816 blocks
__global__ void __launch_bounds__(256)
conv_front(const float4* __restrict__ x, uint2* __restrict__ xh,
           const float4* __restrict__ gw0, uint2* __restrict__ g0h,
           const float4* __restrict__ gw1, uint2* __restrict__ g1h,
           const float4* __restrict__ a0, uint2* __restrict__ w0h)
{
    const int b = blockIdx.x;
    if (b < 256)       half_one(x,   xh,  b * 256 + threadIdx.x);
    else if (b < 512)  half_one(gw0, g0h, (b - 256) * 256 + threadIdx.x);
    else if (b < 768)  half_one(gw1, g1h, (b - 512) * 256 + threadIdx.x);
    else               half_one(a0,  w0h, (b - 768) * 256 + threadIdx.x);
}

// side stream: w1 (2048) + w2 (2048)
__global__ void __launch_bounds__(256)
conv_w12(const float4* __restrict__ a1, uint2* __restrict__ w1h,
         const float4* __restrict__ a2, uint2* __restrict__ w2h)
{
    const int b = blockIdx.x;
    if (b < 2048) half_one(a1, w1h, b * 256 + threadIdx.x);
    else          half_one(a2, w2h, (b - 2048) * 256 + threadIdx.x);
}

// ======== single-pass fp16 GEMM, 64x64 tile, BK=64, 2-stage, reg-pipelined ========
#define LOAD_FRAGS_S(buf, ks)                                                       \
    do {                                                                            \
        const uint32_t achunk = (((uint32_t)((ks) << 1) + ahalf) ^ aswz) << 4;      \
        _Pragma("unroll")                                                           \
        for (int mi = 0; mi < 2; mi++) {                                            \
            const uint32_t roff = (uint32_t)((arow + mi * 16) * 128);               \
            LDSM4(af[buf][mi], Ah + roff + achunk);                                 \
        }                                                                           \
        _Pragma("unroll")                                                           \
        for (int np = 0; np < 2; np++) {                                            \
            const int brow = brow_base + np * 16;                                   \
            const uint32_t boff = (uint32_t)(brow * 128)                            \
                + ((((uint32_t)((ks) << 1) + bk) ^ (uint32_t)(brow & 7)) << 4);     \
            LDSM4(bf[buf][np], Bh + boff);                                          \
        }                                                                           \
    } while (0)

#define DO_MMAS_S(buf)                                                              \
    do {                                                                            \
        _Pragma("unroll")                                                           \
        for (int mi = 0; mi < 2; mi++)                                              \
            _Pragma("unroll")                                                       \
            for (int ni = 0; ni < 4; ni++)                                          \
                MMA16816F(acc[mi][ni], af[buf][mi], bf[buf][ni >> 1][(ni & 1) * 2], \
                          bf[buf][ni >> 1][(ni & 1) * 2 + 1]);                      \
    } while (0)

// z < nExp: expert path (out fp16 Ch if outHalf else fp32 Cf, offset z*WSTRIDE).
// z >= nExp: gating: bias+elu; gOh != null -> fp16 out to gOh (L1),
//            else fp32 out to Cf (L2 -> h2).
__global__ void __launch_bounds__(128, 5)
tgemm(const __half* __restrict__ Ax, const __half* __restrict__ Bw,
      float* __restrict__ Cf, __half* __restrict__ Ch,
      int nExp, int outHalf,
      const __half* __restrict__ gB, const float* __restrict__ gBias,
      __half* __restrict__ gOh)
{
    extern __shared__ __align__(128) char smem[];
    const uint32_t sb = smem_u32(smem);
    const int tid = threadIdx.x;
    const int wid = tid >> 5, lane = tid & 31;
    const int e = blockIdx.z;
    const int bm = blockIdx.y * 64, bn = blockIdx.x * 64;

    const int gating = (e >= nExp);
    const __half* Bp = gating ? gB : Bw + (long)e * WSTRIDE;
    Cf += (long)(gating ? 0 : e) * WSTRIDE;
    Ch += (long)(gating ? 0 : e) * WSTRIDE;

    const int lsub = tid >> 3;   // 0..15
    const int lc16 = tid & 7;

    const __half* tp[2] = { Ax, Bp };
    const int toff[2] = { bm, bn };

    auto load_stage = [&](int kc, int buf) {
        const int k0 = kc << 6;
        const uint32_t base = sb + (uint32_t)buf * 16384u;
        #pragma unroll
        for (int t = 0; t < 2; t++) {
            const __half* P = tp[t];
            #pragma unroll
            for (int it = 0; it < 4; it++) {
                const int row = it * 16 + lsub;
                const uint32_t dst = base + (uint32_t)t * 8192u
                                   + (uint32_t)(row * 128 + ((lc16 ^ (row & 7)) << 4));
                CP16(dst, P + (long)(toff[t] + row) * 512 + k0 + lc16 * 8);
            }
        }
    };

    const int warpM = wid & 1, warpN = wid >> 1;
    const int arow = warpM * 32 + (lane & 15);
    const uint32_t aswz = (uint32_t)(arow & 7);
    const uint32_t ahalf = (uint32_t)(lane >> 4);
    const int q = lane >> 3;
    const int brow_base = warpN * 32 + ((q >> 1) << 3) + (lane & 7);
    const uint32_t bk = (uint32_t)(q & 1);

    float acc[2][4][4] = {};
    uint32_t af[2][2][4], bf[2][2][4];

    load_stage(0, 0);
    asm volatile("cp.async.commit_group;" ::: "memory");

    for (int c = 0; c < 8; c++) {
        if (c + 1 < 8) {
            load_stage(c + 1, (c + 1) & 1);
            asm volatile("cp.async.commit_group;" ::: "memory");
            asm volatile("cp.async.wait_group 1;" ::: "memory");
        } else {
            asm volatile("cp.async.wait_group 0;" ::: "memory");
        }
        __syncthreads();

        const uint32_t S  = sb + (uint32_t)(c & 1) * 16384u;
        const uint32_t Ah = S, Bh = S + 8192u;

        LOAD_FRAGS_S(0, 0);
        #pragma unroll
        for (int ks = 0; ks < 4; ks++) {
            const int cur = ks & 1;
            if (ks < 3) LOAD_FRAGS_S(cur ^ 1, ks + 1);
            DO_MMAS_S(cur);
        }
        __syncthreads();
    }

    const int gr = lane >> 2, gc = (lane & 3) * 2;
    #pragma unroll
    for (int mi = 0; mi < 2; mi++) {
        const int row0 = bm + warpM * 32 + mi * 16 + gr;
        #pragma unroll
        for (int ni = 0; ni < 4; ni++) {
            const int col = bn + warpN * 32 + ni * 8 + gc;
            float v0 = acc[mi][ni][0], v1 = acc[mi][ni][1];
            float v2 = acc[mi][ni][2], v3 = acc[mi][ni][3];
            if (gating) {
                const float b0 = gBias[col], b1 = gBias[col + 1];
                v0 = elu1(v0 + b0); v1 = elu1(v1 + b1);
                v2 = elu1(v2 + b0); v3 = elu1(v3 + b1);
                if (gOh) {
                    *(uint32_t*)&gOh[(long)row0 * 512 + col]       = pack_h2(v0, v1);
                    *(uint32_t*)&gOh[(long)(row0 + 8) * 512 + col] = pack_h2(v2, v3);
                } else {
                    *(float2*)&Cf[(long)row0 * 512 + col]       = make_float2(v0, v1);
                    *(float2*)&Cf[(long)(row0 + 8) * 512 + col] = make_float2(v2, v3);
                }
            } else if (outHalf) {
                *(uint32_t*)&Ch[(long)row0 * 512 + col]       = pack_h2(v0, v1);
                *(uint32_t*)&Ch[(long)(row0 + 8) * 512 + col] = pack_h2(v2, v3);
            } else {
                *(float2*)&Cf[(long)row0 * 512 + col]       = make_float2(v0, v1);
                *(float2*)&Cf[(long)(row0 + 8) * 512 + col] = make_float2(v2, v3);
            }
        }
    }
}

// ---------------- gating softmax ----------------
__global__ void __launch_bounds__(256)
gate_kernel(const float* __restrict__ h, const float* __restrict__ w2,
            const float* __restrict__ b2, float* __restrict__ g)
{
    __shared__ float s[512];
    __shared__ float lg[8];
    const int b = blockIdx.x, tid = threadIdx.x;
    for (int i = tid; i < 512; i += 256) s[i] = h[(long)b * 512 + i];
    __syncthreads();

    const int w = tid >> 5, lane = tid & 31;
    float sum = 0.f;
    for (int i = lane; i < 512; i += 32) sum += s[i] * w2[(long)w * 512 + i];
    #pragma unroll
    for (int o = 16; o > 0; o >>= 1) sum += __shfl_xor_sync(0xffffffffu, sum, o);
    if (lane == 0) lg[w] = sum + b2[w];
    __syncthreads();

    if (tid == 0) {
        float mx = lg[0];
        #pragma unroll
        for (int i = 1; i < 8; i++) mx = fmaxf(mx, lg[i]);
        float ex[8], se = 0.f;
        #pragma unroll
        for (int i = 0; i < 8; i++) { ex[i] = expf(lg[i] - mx); se += ex[i]; }
        float inv = 1.f / se;
        #pragma unroll
        for (int i = 0; i < 8; i++) g[(long)b * 8 + i] = ex[i] * inv;
    }
}

// ---------------- blends ----------------
// fp16-T blend -> fp16 activations (layers 1, 2)
__global__ void __launch_bounds__(256)
blend_half(const uint2* __restrict__ Th, const float* __restrict__ g,
           const float4* __restrict__ beta4, __half* __restrict__ Oh)
{
    const int i4 = blockIdx.x * 256 + threadIdx.x;
    const int base = i4 << 2;
    const int b = base >> 9, h4 = (base & 511) >> 2;
    float4 sum = make_float4(0.f, 0.f, 0.f, 0.f);
    #pragma unroll
    for (int e = 0; e < 8; e++) {
        const float ge = g[b * 8 + e];
        const uint2 U = Th[(e << 16) + i4];
        const float2 f0 = __half22float2(*(const __half2*)&U.x);
        const float2 f1 = __half22float2(*(const __half2*)&U.y);
        const float4 be = beta4[(e << 7) + h4];
        sum.x += ge * (f0.x + be.x); sum.y += ge * (f0.y + be.y);
        sum.z += ge * (f1.x + be.z); sum.w += ge * (f1.y + be.w);
    }
    uint2 H;
    H.x = pack_h2(elu1(sum.x), elu1(sum.y));
    H.y = pack_h2(elu1(sum.z), elu1(sum.w));
    ((uint2*)Oh)[i4] = H;
}

// fp32-T final blend (layer 3)
__global__ void __launch_bounds__(256)
blend_final(const float4* __restrict__ T4, const float* __restrict__ g,
            const float4* __restrict__ beta4, float* __restrict__ out)
{
    const int i4 = blockIdx.x * 256 + threadIdx.x;
    const int base = i4 << 2;
    const int b = base >> 9, h4 = (base & 511) >> 2;
    float4 sum = make_float4(0.f, 0.f, 0.f, 0.f);
    #pragma unroll
    for (int e = 0; e < 8; e++) {
        const float ge = g[b * 8 + e];
        const float4 t = T4[(e << 16) + i4];
        const float4 be = beta4[(e << 7) + h4];
        sum.x += ge * (t.x + be.x); sum.y += ge * (t.y + be.y);
        sum.z += ge * (t.z + be.z); sum.w += ge * (t.w + be.w);
    }
    ((float4*)out)[i4] = sum;
}

// ---------------- launch ----------------
extern "C" void kernel_launch(void* const* d_in, const int* in_sizes, int n_in,
                              void* d_out, int out_size)
{
    const float* x      = (const float*)d_in[0];
    const float* gw0    = (const float*)d_in[1];
    const float* gb0    = (const float*)d_in[2];
    const float* gw1    = (const float*)d_in[3];
    const float* gb1    = (const float*)d_in[4];
    const float* gw2    = (const float*)d_in[5];
    const float* gb2    = (const float*)d_in[6];
    const float* alpha0 = (const float*)d_in[7];
    const float* beta0  = (const float*)d_in[8];
    const float* alpha1 = (const float*)d_in[9];
    const float* beta1  = (const float*)d_in[10];
    const float* alpha2 = (const float*)d_in[11];
    const float* beta2  = (const float*)d_in[12];
    float* out = (float*)d_out;

    float *h2, *gp, *T;
    cudaGetSymbolAddress((void**)&h2, d_h2);
    cudaGetSymbolAddress((void**)&gp, d_g);
    cudaGetSymbolAddress((void**)&T,  d_T);
    __half* Th = (__half*)T;

    __half *xh, *ah, *g0h, *g1h, *w0h, *w1h, *w2h;
    cudaGetSymbolAddress((void**)&xh,  d_xh);  cudaGetSymbolAddress((void**)&ah,  d_ah);
    cudaGetSymbolAddress((void**)&g0h, d_g0h); cudaGetSymbolAddress((void**)&g1h, d_g1h);
    cudaGetSymbolAddress((void**)&w0h, d_w0h); cudaGetSymbolAddress((void**)&w1h, d_w1h);
    cudaGetSymbolAddress((void**)&w2h, d_w2h);

    const int SMEM_SZ = 2 * 16384;   // 32KB/CTA
    cudaFuncSetAttribute(tgemm, cudaFuncAttributeMaxDynamicSharedMemorySize, SMEM_SZ);

    dim3 gMerged(8, 8, 9), g8(8, 8, 8), gGate(8, 8, 1);
    const int BLEND_B = (BSZ * HD / 4) / 256;

    // side stream for w1/w2 conversion (overlaps merged GEMM + gate chain)
    cudaStream_t s2;
    cudaStreamCreate(&s2);
    cudaEvent_t eFork, eJoin;
    cudaEventCreateWithFlags(&eFork, cudaEventDisableTiming);
    cudaEventCreateWithFlags(&eJoin, cudaEventDisableTiming);

    cudaEventRecord(eFork, 0);
    cudaStreamWaitEvent(s2, eFork, 0);
    conv_w12<<<4096, 256, 0, s2>>>((const float4*)alpha1, (uint2*)w1h,
                                   (const float4*)alpha2, (uint2*)w2h);
    cudaEventRecord(eJoin, s2);

    // front conversions (x, gw0, gw1, w0 -> fp16)
    conv_front<<<2816, 256>>>((const float4*)x, (uint2*)xh,
                              (const float4*)gw0, (uint2*)g0h,
                              (const float4*)gw1, (uint2*)g1h,
                              (const float4*)alpha0, (uint2*)w0h);

    // merged: expert layer-1 (z 0..7, T fp16) + gating L1 (z 8 -> ah fp16)
    tgemm<<<gMerged, 128, SMEM_SZ>>>(xh, w0h, T, Th, 8, 1, g0h, gb0, ah);

    // gating L2 (bias+elu fp32 -> h2) + softmax
    tgemm<<<gGate, 128, SMEM_SZ>>>(ah, nullptr, h2, nullptr, 0, 0, g1h, gb1, nullptr);
    gate_kernel<<<BSZ, 256>>>(h2, gw2, gb2, gp);

    // expert layer 1 blend (T fp16 -> ah fp16)
    blend_half<<<BLEND_B, 256>>>((const uint2*)Th, gp, (const float4*)beta0, ah);

    // join w1/w2 conversion before layer-2 GEMM
    cudaStreamWaitEvent(0, eJoin, 0);

    // expert layer 2 (T fp16)
    tgemm<<<g8, 128, SMEM_SZ>>>(ah, w1h, T, Th, 8, 1, nullptr, nullptr, nullptr);
    blend_half<<<BLEND_B, 256>>>((const uint2*)Th, gp, (const float4*)beta1, ah);

    // expert layer 3 (T fp32) + final blend
    tgemm<<<g8, 128, SMEM_SZ>>>(ah, w2h, T, Th, 8, 0, nullptr, nullptr, nullptr);
    blend_final<<<BLEND_B, 256>>>((const float4*)T, gp, (const float4*)beta2, out);
}

// round 14
// speedup vs baseline: 2.6217x; 1.0482x over previous
#include <cuda_runtime.h>
#include <cuda_fp16.h>
#include <math.h>
#include <cstdint>

#define BSZ 512
#define FD  512
#define HD  512
#define ED  8
#define OD  512
#define SK  4
#define WSTRIDE 262144L   // 512*512

// ---------------- scratch ----------------
__device__ float d_h2[BSZ * HD];
__device__ float d_g [BSZ * ED];
__device__ float d_T [ED * BSZ * HD];          // fp32 T (layer 3); fp16 T aliases
__device__ float d_part[SK * BSZ * HD];

__device__ __align__(16) __half d_xh[BSZ * FD];
__device__ __align__(16) __half d_ah[BSZ * FD];
__device__ __align__(16) __half d_gh[BSZ * FD];   // gating L1 activations
__device__ __align__(16) __half d_g0h[HD * FD];
__device__ __align__(16) __half d_g1h[HD * HD];
__device__ __align__(16) __half d_w0h[ED * HD * FD];
__device__ __align__(16) __half d_w1h[ED * HD * HD];
__device__ __align__(16) __half d_w2h[ED * OD * HD];

__device__ __forceinline__ float elu1(float v) { return v > 0.f ? v : expm1f(v); }

__device__ __forceinline__ uint32_t smem_u32(const void* p) {
    uint32_t a;
    asm("{ .reg .u64 t; cvta.to.shared.u64 t, %1; cvt.u32.u64 %0, t; }" : "=r"(a) : "l"(p));
    return a;
}

#define CP16(dst, src) \
    asm volatile("cp.async.cg.shared.global [%0], [%1], 16;" :: "r"(dst), "l"(src))

#define LDSM4(r, addr) \
    asm volatile("ldmatrix.sync.aligned.m8n8.x4.shared.b16 {%0,%1,%2,%3}, [%4];" \
                 : "=r"((r)[0]), "=r"((r)[1]), "=r"((r)[2]), "=r"((r)[3]) : "r"(addr))

#define MMA16816F(d, a, b0, b1) \
    asm volatile("mma.sync.aligned.m16n8k16.row.col.f32.f16.f16.f32 " \
                 "{%0,%1,%2,%3},{%4,%5,%6,%7},{%8,%9},{%0,%1,%2,%3};" \
                 : "+f"((d)[0]), "+f"((d)[1]), "+f"((d)[2]), "+f"((d)[3]) \
                 : "r"((a)[0]), "r"((a)[1]), "r"((a)[2]), "r"((a)[3]), "r"(b0), "r"(b1))

__device__ __forceinline__ uint32_t pack_h2(float a, float b) {
    __half2 h = __floats2half2_rn(a, b);
    return *(uint32_t*)&h;
}

// ---------------- conversions ----------------
__device__ __forceinline__ void half_one(const float4* in, uint2* hi, int i) {
    float4 v = in[i];
    uint2 H;
    H.x = pack_h2(v.x, v.y); H.y = pack_h2(v.z, v.w);
    hi[i] = H;
}

__global__ void __launch_bounds__(256)
conv_front(const float4* __restrict__ x, uint2* __restrict__ xh,
           const float4* __restrict__ gw0, uint2* __restrict__ g0h,
           const float4* __restrict__ gw1, uint2* __restrict__ g1h,
           const float4* __restrict__ a0, uint2* __restrict__ w0h)
{
    const int b = blockIdx.x;
    if (b < 256)       half_one(x,   xh,  b * 256 + threadIdx.x);
    else if (b < 512)  half_one(gw0, g0h, (b - 256) * 256 + threadIdx.x);
    else if (b < 768)  half_one(gw1, g1h, (b - 512) * 256 + threadIdx.x);
    else               half_one(a0,  w0h, (b - 768) * 256 + threadIdx.x);
}

__global__ void __launch_bounds__(256)
conv_w12(const float4* __restrict__ a1, uint2* __restrict__ w1h,
         const float4* __restrict__ a2, uint2* __restrict__ w2h)
{
    const int b = blockIdx.x;
    if (b < 2048) half_one(a1, w1h, b * 256 + threadIdx.x);
    else          half_one(a2, w2h, (b - 2048) * 256 + threadIdx.x);
}

// ======== single-pass fp16 GEMM machinery (64x64 tile, BK=64, 2-stage) ========
#define LOAD_FRAGS_S(buf, ks)                                                       \
    do {                                                                            \
        const uint32_t achunk = (((uint32_t)((ks) << 1) + ahalf) ^ aswz) << 4;      \
        _Pragma("unroll")                                                           \
        for (int mi = 0; mi < 2; mi++) {                                            \
            const uint32_t roff = (uint32_t)((arow + mi * 16) * 128);               \
            LDSM4(af[buf][mi], Ah + roff + achunk);                                 \
        }                                                                           \
        _Pragma("unroll")                                                           \
        for (int np = 0; np < 2; np++) {                                            \
            const int brow = brow_base + np * 16;                                   \
            const uint32_t boff = (uint32_t)(brow * 128)                            \
                + ((((uint32_t)((ks) << 1) + bk) ^ (uint32_t)(brow & 7)) << 4);     \
            LDSM4(bf[buf][np], Bh + boff);                                          \
        }                                                                           \
    } while (0)

#define DO_MMAS_S(buf)                                                              \
    do {                                                                            \
        _Pragma("unroll")                                                           \
        for (int mi = 0; mi < 2; mi++)                                              \
            _Pragma("unroll")                                                       \
            for (int ni = 0; ni < 4; ni++)                                          \
                MMA16816F(acc[mi][ni], af[buf][mi], bf[buf][ni >> 1][(ni & 1) * 2], \
                          bf[buf][ni >> 1][(ni & 1) * 2 + 1]);                      \
    } while (0)

#define GEMM_SETUP()                                                                \
    extern __shared__ __align__(128) char smem[];                                   \
    const uint32_t sb = smem_u32(smem);                                             \
    const int tid = threadIdx.x;                                                    \
    const int wid = tid >> 5, lane = tid & 31;                                      \
    const int bm = blockIdx.y * 64, bn = blockIdx.x * 64;                           \
    const int lsub = tid >> 3;                                                      \
    const int lc16 = tid & 7;                                                       \
    const int warpM = wid & 1, warpN = wid >> 1;                                    \
    const int arow = warpM * 32 + (lane & 15);                                      \
    const uint32_t aswz = (uint32_t)(arow & 7);                                     \
    const uint32_t ahalf = (uint32_t)(lane >> 4);                                   \
    const int q = lane >> 3;                                                        \
    const int brow_base = warpN * 32 + ((q >> 1) << 3) + (lane & 7);                \
    const uint32_t bk = (uint32_t)(q & 1)

// ---------------- main GEMM ----------------
__global__ void __launch_bounds__(128, 5)
tgemm(const __half* __restrict__ Ax, const __half* __restrict__ Bw,
      float* __restrict__ Cf, __half* __restrict__ Ch,
      int nExp, int outHalf,
      const __half* __restrict__ gB, const float* __restrict__ gBias,
      __half* __restrict__ gOh)
{
    GEMM_SETUP();
    const int e = blockIdx.z;
    const int gating = (e >= nExp);
    const __half* Bp = gating ? gB : Bw + (long)e * WSTRIDE;
    Cf += (long)(gating ? 0 : e) * WSTRIDE;
    Ch += (long)(gating ? 0 : e) * WSTRIDE;

    const __half* tp[2] = { Ax, Bp };
    const int toff[2] = { bm, bn };

    auto load_stage = [&](int kc, int buf) {
        const int k0 = kc << 6;
        const uint32_t base = sb + (uint32_t)buf * 16384u;
        #pragma unroll
        for (int t = 0; t < 2; t++) {
            const __half* P = tp[t];
            #pragma unroll
            for (int it = 0; it < 4; it++) {
                const int row = it * 16 + lsub;
                const uint32_t dst = base + (uint32_t)t * 8192u
                                   + (uint32_t)(row * 128 + ((lc16 ^ (row & 7)) << 4));
                CP16(dst, P + (long)(toff[t] + row) * 512 + k0 + lc16 * 8);
            }
        }
    };

    float acc[2][4][4] = {};
    uint32_t af[2][2][4], bf[2][2][4];

    load_stage(0, 0);
    asm volatile("cp.async.commit_group;" ::: "memory");

    for (int c = 0; c < 8; c++) {
        if (c + 1 < 8) {
            load_stage(c + 1, (c + 1) & 1);
            asm volatile("cp.async.commit_group;" ::: "memory");
            asm volatile("cp.async.wait_group 1;" ::: "memory");
        } else {
            asm volatile("cp.async.wait_group 0;" ::: "memory");
        }
        __syncthreads();

        const uint32_t S  = sb + (uint32_t)(c & 1) * 16384u;
        const uint32_t Ah = S, Bh = S + 8192u;

        LOAD_FRAGS_S(0, 0);
        #pragma unroll
        for (int ks = 0; ks < 4; ks++) {
            const int cur = ks & 1;
            if (ks < 3) LOAD_FRAGS_S(cur ^ 1, ks + 1);
            DO_MMAS_S(cur);
        }
        __syncthreads();
    }

    const int gr = lane >> 2, gc = (lane & 3) * 2;
    #pragma unroll
    for (int mi = 0; mi < 2; mi++) {
        const int row0 = bm + warpM * 32 + mi * 16 + gr;
        #pragma unroll
        for (int ni = 0; ni < 4; ni++) {
            const int col = bn + warpN * 32 + ni * 8 + gc;
            float v0 = acc[mi][ni][0], v1 = acc[mi][ni][1];
            float v2 = acc[mi][ni][2], v3 = acc[mi][ni][3];
            if (gating) {
                const float b0 = gBias[col], b1 = gBias[col + 1];
                v0 = elu1(v0 + b0); v1 = elu1(v1 + b1);
                v2 = elu1(v2 + b0); v3 = elu1(v3 + b1);
                if (gOh) {
                    *(uint32_t*)&gOh[(long)row0 * 512 + col]       = pack_h2(v0, v1);
                    *(uint32_t*)&gOh[(long)(row0 + 8) * 512 + col] = pack_h2(v2, v3);
                } else {
                    *(float2*)&Cf[(long)row0 * 512 + col]       = make_float2(v0, v1);
                    *(float2*)&Cf[(long)(row0 + 8) * 512 + col] = make_float2(v2, v3);
                }
            } else if (outHalf) {
                *(uint32_t*)&Ch[(long)row0 * 512 + col]       = pack_h2(v0, v1);
                *(uint32_t*)&Ch[(long)(row0 + 8) * 512 + col] = pack_h2(v2, v3);
            } else {
                *(float2*)&Cf[(long)row0 * 512 + col]       = make_float2(v0, v1);
                *(float2*)&Cf[(long)(row0 + 8) * 512 + col] = make_float2(v2, v3);
            }
        }
    }
}

// ---------------- split-K gate-L2: grid (8,8,SK), z covers 2 chunks (K=128) ----------------
__global__ void __launch_bounds__(128, 5)
tgemm_sk(const __half* __restrict__ Ax, const __half* __restrict__ Bp,
         float* __restrict__ part)
{
    GEMM_SETUP();
    const int z = blockIdx.z;
    float* C = part + (long)z * BSZ * HD;

    const __half* tp[2] = { Ax, Bp };
    const int toff[2] = { bm, bn };

    auto load_stage = [&](int kc, int buf) {
        const int k0 = kc << 6;
        const uint32_t base = sb + (uint32_t)buf * 16384u;
        #pragma unroll
        for (int t = 0; t < 2; t++) {
            const __half* P = tp[t];
            #pragma unroll
            for (int it = 0; it < 4; it++) {
                const int row = it * 16 + lsub;
                const uint32_t dst = base + (uint32_t)t * 8192u
                                   + (uint32_t)(row * 128 + ((lc16 ^ (row & 7)) << 4));
                CP16(dst, P + (long)(toff[t] + row) * 512 + k0 + lc16 * 8);
            }
        }
    };

    float acc[2][4][4] = {};
    uint32_t af[2][2][4], bf[2][2][4];

    load_stage(z * 2, 0);
    asm volatile("cp.async.commit_group;" ::: "memory");
    load_stage(z * 2 + 1, 1);
    asm volatile("cp.async.commit_group;" ::: "memory");

    #pragma unroll
    for (int c = 0; c < 2; c++) {
        if (c == 0) asm volatile("cp.async.wait_group 1;" ::: "memory");
        else        asm volatile("cp.async.wait_group 0;" ::: "memory");
        __syncthreads();

        const uint32_t S  = sb + (uint32_t)(c & 1) * 16384u;
        const uint32_t Ah = S, Bh = S + 8192u;

        LOAD_FRAGS_S(0, 0);
        #pragma unroll
        for (int ks = 0; ks < 4; ks++) {
            const int cur = ks & 1;
            if (ks < 3) LOAD_FRAGS_S(cur ^ 1, ks + 1);
            DO_MMAS_S(cur);
        }
        __syncthreads();
    }

    const int gr = lane >> 2, gc = (lane & 3) * 2;
    #pragma unroll
    for (int mi = 0; mi < 2; mi++) {
        const int row0 = bm + warpM * 32 + mi * 16 + gr;
        #pragma unroll
        for (int ni = 0; ni < 4; ni++) {
            const int col = bn + warpN * 32 + ni * 8 + gc;
            *(float2*)&C[(long)row0 * 512 + col]       = make_float2(acc[mi][ni][0], acc[mi][ni][1]);
            *(float2*)&C[(long)(row0 + 8) * 512 + col] = make_float2(acc[mi][ni][2], acc[mi][ni][3]);
        }
    }
}

__global__ void __launch_bounds__(256)
reduce_gate(const float4* __restrict__ part, const float* __restrict__ bias,
            float4* __restrict__ h2)
{
    const int i4 = blockIdx.x * 256 + threadIdx.x;
    const int col = (i4 << 2) & 511;
    float4 s = part[i4];
    #pragma unroll
    for (int z = 1; z < SK; z++) {
        const float4 p = part[z * (BSZ * HD / 4) + i4];
        s.x += p.x; s.y += p.y; s.z += p.z; s.w += p.w;
    }
    s.x = elu1(s.x + bias[col]);     s.y = elu1(s.y + bias[col + 1]);
    s.z = elu1(s.z + bias[col + 2]); s.w = elu1(s.w + bias[col + 3]);
    h2[i4] = s;
}

// ---------------- gating softmax ----------------
__global__ void __launch_bounds__(256)
gate_kernel(const float* __restrict__ h, const float* __restrict__ w2,
            const float* __restrict__ b2, float* __restrict__ g)
{
    __shared__ float s[512];
    __shared__ float lg[8];
    const int b = blockIdx.x, tid = threadIdx.x;
    for (int i = tid; i < 512; i += 256) s[i] = h[(long)b * 512 + i];
    __syncthreads();

    const int w = tid >> 5, lane = tid & 31;
    float sum = 0.f;
    for (int i = lane; i < 512; i += 32) sum += s[i] * w2[(long)w * 512 + i];
    #pragma unroll
    for (int o = 16; o > 0; o >>= 1) sum += __shfl_xor_sync(0xffffffffu, sum, o);
    if (lane == 0) lg[w] = sum + b2[w];
    __syncthreads();

    if (tid == 0) {
        float mx = lg[0];
        #pragma unroll
        for (int i = 1; i < 8; i++) mx = fmaxf(mx, lg[i]);
        float ex[8], se = 0.f;
        #pragma unroll
        for (int i = 0; i < 8; i++) { ex[i] = expf(lg[i] - mx); se += ex[i]; }
        float inv = 1.f / se;
        #pragma unroll
        for (int i = 0; i < 8; i++) g[(long)b * 8 + i] = ex[i] * inv;
    }
}

// ---------------- blends ----------------
__global__ void __launch_bounds__(256)
blend_half(const uint2* __restrict__ Th, const float* __restrict__ g,
           const float4* __restrict__ beta4, __half* __restrict__ Oh)
{
    const int i4 = blockIdx.x * 256 + threadIdx.x;
    const int base = i4 << 2;
    const int b = base >> 9, h4 = (base & 511) >> 2;
    float4 sum = make_float4(0.f, 0.f, 0.f, 0.f);
    #pragma unroll
    for (int e = 0; e < 8; e++) {
        const float ge = g[b * 8 + e];
        const uint2 U = Th[(e << 16) + i4];
        const float2 f0 = __half22float2(*(const __half2*)&U.x);
        const float2 f1 = __half22float2(*(const __half2*)&U.y);
        const float4 be = beta4[(e << 7) + h4];
        sum.x += ge * (f0.x + be.x); sum.y += ge * (f0.y + be.y);
        sum.z += ge * (f1.x + be.z); sum.w += ge * (f1.y + be.w);
    }
    uint2 H;
    H.x = pack_h2(elu1(sum.x), elu1(sum.y));
    H.y = pack_h2(elu1(sum.z), elu1(sum.w));
    ((uint2*)Oh)[i4] = H;
}

__global__ void __launch_bounds__(256)
blend_final(const float4* __restrict__ T4, const float* __restrict__ g,
            const float4* __restrict__ beta4, float* __restrict__ out)
{
    const int i4 = blockIdx.x * 256 + threadIdx.x;
    const int base = i4 << 2;
    const int b = base >> 9, h4 = (base & 511) >> 2;
    float4 sum = make_float4(0.f, 0.f, 0.f, 0.f);
    #pragma unroll
    for (int e = 0; e < 8; e++) {
        const float ge = g[b * 8 + e];
        const float4 t = T4[(e << 16) + i4];
        const float4 be = beta4[(e << 7) + h4];
        sum.x += ge * (t.x + be.x); sum.y += ge * (t.y + be.y);
        sum.z += ge * (t.z + be.z); sum.w += ge * (t.w + be.w);
    }
    ((float4*)out)[i4] = sum;
}

// ---------------- launch ----------------
extern "C" void kernel_launch(void* const* d_in, const int* in_sizes, int n_in,
                              void* d_out, int out_size)
{
    const float* x      = (const float*)d_in[0];
    const float* gw0    = (const float*)d_in[1];
    const float* gb0    = (const float*)d_in[2];
    const float* gw1    = (const float*)d_in[3];
    const float* gb1    = (const float*)d_in[4];
    const float* gw2    = (const float*)d_in[5];
    const float* gb2    = (const float*)d_in[6];
    const float* alpha0 = (const float*)d_in[7];
    const float* beta0  = (const float*)d_in[8];
    const float* alpha1 = (const float*)d_in[9];
    const float* beta1  = (const float*)d_in[10];
    const float* alpha2 = (const float*)d_in[11];
    const float* beta2  = (const float*)d_in[12];
    float* out = (float*)d_out;

    float *h2, *gp, *T, *part;
    cudaGetSymbolAddress((void**)&h2, d_h2);
    cudaGetSymbolAddress((void**)&gp, d_g);
    cudaGetSymbolAddress((void**)&T,  d_T);
    cudaGetSymbolAddress((void**)&part, d_part);
    __half* Th = (__half*)T;

    __half *xh, *ah, *gh, *g0h, *g1h, *w0h, *w1h, *w2h;
    cudaGetSymbolAddress((void**)&xh,  d_xh);  cudaGetSymbolAddress((void**)&ah,  d_ah);
    cudaGetSymbolAddress((void**)&gh,  d_gh);
    cudaGetSymbolAddress((void**)&g0h, d_g0h); cudaGetSymbolAddress((void**)&g1h, d_g1h);
    cudaGetSymbolAddress((void**)&w0h, d_w0h); cudaGetSymbolAddress((void**)&w1h, d_w1h);
    cudaGetSymbolAddress((void**)&w2h, d_w2h);

    const int SMEM_SZ = 2 * 16384;   // 32KB/CTA -> 5 CTAs/SM
    cudaFuncSetAttribute(tgemm,    cudaFuncAttributeMaxDynamicSharedMemorySize, SMEM_SZ);
    cudaFuncSetAttribute(tgemm_sk, cudaFuncAttributeMaxDynamicSharedMemorySize, SMEM_SZ);

    dim3 g8(8, 8, 8), gGate(8, 8, 1), gSK(8, 8, SK);
    const int BLEND_B = (BSZ * HD / 4) / 256;
    const int NSMALL4 = (512 * 512) / 4;

    // ONE auxiliary stream (R12-verified resource profile): carries w1/w2
    // conversion then the whole gating network, overlapped with main-stream
    // front conversion + expert-L1 GEMM.
    cudaStream_t s2;
    cudaStreamCreate(&s2);
    cudaEvent_t eStart, eFront, eGate, eW12;
    cudaEventCreateWithFlags(&eStart, cudaEventDisableTiming);
    cudaEventCreateWithFlags(&eFront, cudaEventDisableTiming);
    cudaEventCreateWithFlags(&eGate,  cudaEventDisableTiming);
    cudaEventCreateWithFlags(&eW12,   cudaEventDisableTiming);

    cudaEventRecord(eStart, 0);
    cudaStreamWaitEvent(s2, eStart, 0);

    // s2: w1/w2 conversion (independent of front)
    conv_w12<<<4096, 256, 0, s2>>>((const float4*)alpha1, (uint2*)w1h,
                                   (const float4*)alpha2, (uint2*)w2h);
    cudaEventRecord(eW12, s2);

    // main: front conversions (x, gw0, gw1, w0)
    conv_front<<<2816, 256>>>((const float4*)x, (uint2*)xh,
                              (const float4*)gw0, (uint2*)g0h,
                              (const float4*)gw1, (uint2*)g1h,
                              (const float4*)alpha0, (uint2*)w0h);
    cudaEventRecord(eFront, 0);

    // s2: gating network (after front), concurrent with expert L1 GEMM
    cudaStreamWaitEvent(s2, eFront, 0);
    tgemm<<<gGate, 128, SMEM_SZ, s2>>>(xh, nullptr, h2, nullptr, 0, 0, g0h, gb0, gh);
    tgemm_sk<<<gSK, 128, SMEM_SZ, s2>>>(gh, g1h, part);
    reduce_gate<<<NSMALL4 / 256, 256, 0, s2>>>((const float4*)part, gb1, (float4*)h2);
    gate_kernel<<<BSZ, 256, 0, s2>>>(h2, gw2, gb2, gp);
    cudaEventRecord(eGate, s2);

    // main: expert layer-1 GEMM (T fp16), then join gate before blend
    tgemm<<<g8, 128, SMEM_SZ>>>(xh, w0h, T, Th, 8, 1, nullptr, nullptr, nullptr);
    cudaStreamWaitEvent(0, eGate, 0);
    blend_half<<<BLEND_B, 256>>>((const uint2*)Th, gp, (const float4*)beta0, ah);

    // join w1/w2 conversion before layer-2 GEMM
    cudaStreamWaitEvent(0, eW12, 0);

    // expert layer 2 (T fp16)
    tgemm<<<g8, 128, SMEM_SZ>>>(ah, w1h, T, Th, 8, 1, nullptr, nullptr, nullptr);
    blend_half<<<BLEND_B, 256>>>((const uint2*)Th, gp, (const float4*)beta1, ah);

    // expert layer 3 (T fp32) + final blend
    tgemm<<<g8, 128, SMEM_SZ>>>(ah, w2h, T, Th, 8, 0, nullptr, nullptr, nullptr);
    blend_final<<<BLEND_B, 256>>>((const float4*)T, gp, (const float4*)beta2, out);
}